// round 13
// baseline (speedup 1.0000x reference)
#include <cuda_runtime.h>
#include <cuda_bf16.h>
#include <cuda_fp16.h>
#include <cstdint>

typedef unsigned long long ull;
typedef unsigned int u32;

// ---------------- scratch (static __device__, no allocations) ----------------
static __device__ float g_b0[4096];               // b_ih+b_hh
static __device__ float g_bf[4096];               // + W_ih@b_out
static __device__ u32   g_flag[129][4][16];       // per-(t,mT,chunk) producer counters (target 2)
// fp16 HI-ONLY weight tiles, gate-paired rows, SW128: [src][nT 32][chunk 16][128x64]
static __device__ __align__(256) __half g_wbf[2][32][16][8192];
// fp16 HI-ONLY hidden tiles: [t 0..128][mT 4][chunk 16][128x64]
static __device__ __align__(256) __half g_hbf[129][4][16][8192];
// fp16 output-weight tiles: [nOT 2][chunk 16][part 2][128x64] (hi at part 0)
static __device__ __align__(256) __half g_obf[2][16][2][8192];
// prep-GEMM operands (bf16 split, 3-pass prep path)
static __device__ __align__(256) __nv_bfloat16 g_pA[32][4][2][8192];
static __device__ __align__(256) __nv_bfloat16 g_pB[16][4][2][4096];

// ---------------- helpers ----------------
__device__ __forceinline__ float sigm(float x) { return 1.0f / (1.0f + __expf(-x)); }
__device__ __forceinline__ u32 swz(u32 x) { return x ^ ((x >> 3) & 0x70); }
__device__ __forceinline__ u32 smem_u32(const void* p) {
    u32 a; asm("{ .reg .u64 t; cvta.to.shared.u64 t, %1; cvt.u32.u64 %0, t; }" : "=r"(a) : "l"(p));
    return a;
}
__device__ __forceinline__ void cpa16(u32 dst, const void* src) {
    asm volatile("cp.async.cg.shared.global [%0], [%1], 16;" :: "r"(dst), "l"(src));
}
#define CP_COMMIT() asm volatile("cp.async.commit_group;" ::: "memory")
#define CP_WAIT0()  asm volatile("cp.async.wait_group 0;" ::: "memory")

// ---- bulk copy + mbarrier ----
__device__ __forceinline__ void bulk_g2s(u32 dst, const void* src, u32 bytes, u32 mbar) {
    asm volatile("cp.async.bulk.shared::cta.global.mbarrier::complete_tx::bytes [%0], [%1], %2, [%3];"
                 :: "r"(dst), "l"(src), "r"(bytes), "r"(mbar) : "memory");
}
__device__ __forceinline__ void mbar_init(u32 a, u32 cnt) {
    asm volatile("mbarrier.init.shared.b64 [%0], %1;" :: "r"(a), "r"(cnt) : "memory");
}
__device__ __forceinline__ void mbar_expect(u32 a, u32 tx) {
    asm volatile("mbarrier.arrive.expect_tx.shared.b64 _, [%0], %1;" :: "r"(a), "r"(tx) : "memory");
}
__device__ __forceinline__ void mbar_wait(u32 a, u32 ph) {
    asm volatile("{\n\t.reg .pred P;\n\t"
                 "WL_%=:\n\t"
                 "mbarrier.try_wait.parity.acquire.cta.shared::cta.b64 P, [%0], %1, 0x989680;\n\t"
                 "@P bra.uni WD_%=;\n\t"
                 "bra.uni WL_%=;\n\t"
                 "WD_%=:\n\t}"
                 :: "r"(a), "r"(ph) : "memory");
}
// tid0-only relaxed poll (fast path = single load); caller issues fence.acquire.gpu after
__device__ __forceinline__ void flag_wait(const u32* p) {
    u32 v;
    asm volatile("ld.relaxed.gpu.global.u32 %0, [%1];" : "=r"(v) : "l"(p) : "memory");
    while (v < 2) {
        asm volatile("nanosleep.u32 32;");
        asm volatile("ld.relaxed.gpu.global.u32 %0, [%1];" : "=r"(v) : "l"(p) : "memory");
    }
}
#define FENCE_ACQ() asm volatile("fence.acquire.gpu;" ::: "memory")

__device__ __forceinline__ void ldsm4(u32* r, u32 addr) {
    asm volatile("ldmatrix.sync.aligned.m8n8.x4.shared.b16 {%0,%1,%2,%3}, [%4];"
                 : "=r"(r[0]), "=r"(r[1]), "=r"(r[2]), "=r"(r[3]) : "r"(addr));
}
__device__ __forceinline__ void mma_bf16(float* d, const u32* a, const u32* b) {
    asm volatile("mma.sync.aligned.m16n8k16.row.col.f32.bf16.bf16.f32 "
                 "{%0,%1,%2,%3}, {%4,%5,%6,%7}, {%8,%9}, {%0,%1,%2,%3};"
                 : "+f"(d[0]), "+f"(d[1]), "+f"(d[2]), "+f"(d[3])
                 : "r"(a[0]), "r"(a[1]), "r"(a[2]), "r"(a[3]), "r"(b[0]), "r"(b[1]));
}
__device__ __forceinline__ void mma_f16(float* d, const u32* a, const u32* b) {
    asm volatile("mma.sync.aligned.m16n8k16.row.col.f32.f16.f16.f32 "
                 "{%0,%1,%2,%3}, {%4,%5,%6,%7}, {%8,%9}, {%0,%1,%2,%3};"
                 : "+f"(d[0]), "+f"(d[1]), "+f"(d[2]), "+f"(d[3])
                 : "r"(a[0]), "r"(a[1]), "r"(a[2]), "r"(a[3]), "r"(b[0]), "r"(b[1]));
}
__device__ __forceinline__ void split_h16(float v, __half& h, __half& l) {
    h = __float2half_rn(v);
    l = __float2half_rn(v - __half2float(h));
}
__device__ __forceinline__ u32 pack2h(float v0, float v1) {
    __half h0 = __float2half_rn(v0), h1 = __float2half_rn(v1);
    return (u32)__half_as_ushort(h0) | ((u32)__half_as_ushort(h1) << 16);
}
__device__ __forceinline__ u32 pack_split2h(float v0, float v1, u32& lo_out) {
    __half h0, l0, h1, l1;
    split_h16(v0, h0, l0); split_h16(v1, h1, l1);
    lo_out = (u32)__half_as_ushort(l0) | ((u32)__half_as_ushort(l1) << 16);
    return (u32)__half_as_ushort(h0) | ((u32)__half_as_ushort(h1) << 16);
}
__device__ __forceinline__ void split_bf(float v, __nv_bfloat16& h, __nv_bfloat16& l) {
    h = __float2bfloat16(v);
    l = __float2bfloat16(v - __bfloat162float(h));
}
// gate-paired row -> j (j = gate*1024 + cell)
__device__ __forceinline__ int rowj(int nT, int n) {
    int half = n >> 6, m = n & 63;
    return (half * 2 + (m & 1)) * 1024 + nT * 32 + (m >> 1);
}

// ---------------- merged prep: convs + bias + flag init, one launch ----------------
__global__ void conv_all(const float* __restrict__ Whh, const float* __restrict__ Wih,
                         const float* __restrict__ Wout, const float* __restrict__ enc,
                         const float* __restrict__ bih, const float* __restrict__ bhh,
                         const float* __restrict__ bout)
{
    int b = blockIdx.x;
    int tid = threadIdx.x, w = tid >> 5, lane = tid & 31;

    if (b < 512) {                      // conv_w0: Whh -> g_wbf[0]
        int chunk = b & 15, nT = b >> 4;
        char* th = (char*)&g_wbf[0][nT][chunk][0];
#pragma unroll
        for (int r = 0; r < 16; r++) {
            int n = r * 8 + w;
            const float2 v2 = *(const float2*)&Whh[(size_t)rowj(nT, n) * 1024 + chunk * 64 + lane * 2];
            u32 off = swz((u32)(n * 128 + lane * 4));
            *(u32*)(th + off) = pack2h(v2.x, v2.y);
        }
    } else if (b < 640) {               // conv_wih -> g_pA (bf16 split)
        int idx = b - 512, oc = idx & 3, nT = idx >> 2;
        char* th = (char*)&g_pA[nT][oc][0][0];
        char* tl = th + 16384;
#pragma unroll
        for (int r = 0; r < 16; r++) {
            int n = r * 8 + w;
            const float2 v2 = *(const float2*)&Wih[(size_t)rowj(nT, n) * 256 + oc * 64 + lane * 2];
            __nv_bfloat16 h0, l0, h1, l1;
            split_bf(v2.x, h0, l0); split_bf(v2.y, h1, l1);
            u32 hi = (u32)__bfloat16_as_ushort(h0) | ((u32)__bfloat16_as_ushort(h1) << 16);
            u32 lo = (u32)__bfloat16_as_ushort(l0) | ((u32)__bfloat16_as_ushort(l1) << 16);
            u32 off = swz((u32)(n * 128 + lane * 4));
            *(u32*)(th + off) = hi;
            *(u32*)(tl + off) = lo;
        }
    } else if (b < 704) {               // conv_woutT -> g_pB (bf16 split)
        int idx = b - 640, oc = idx & 3, kc = idx >> 2;
        int k = tid & 63, og = tid >> 6;
        char* th = (char*)&g_pB[kc][oc][0][0];
        char* tl = th + 8192;
#pragma unroll
        for (int i = 0; i < 16; i++) {
            int oo = og * 16 + i;
            float v = Wout[(size_t)(oc * 64 + oo) * 1024 + kc * 64 + k];
            __nv_bfloat16 h, l; split_bf(v, h, l);
            u32 off = swz((u32)(k * 128 + oo * 2));
            *(__nv_bfloat16*)(th + off) = h;
            *(__nv_bfloat16*)(tl + off) = l;
        }
    } else if (b < 736) {               // conv_obf -> g_obf (fp16 split; hi used)
        int idx = b - 704, chunk = idx & 15, nOT = idx >> 4;
        char* th = (char*)&g_obf[nOT][chunk][0][0];
        char* tl = th + 16384;
#pragma unroll
        for (int r = 0; r < 16; r++) {
            int n = r * 8 + w;
            const float2 v2 = *(const float2*)&Wout[(size_t)(nOT * 128 + n) * 1024 + chunk * 64 + lane * 2];
            u32 lo, hi = pack_split2h(v2.x, v2.y, lo);
            u32 off = swz((u32)(n * 128 + lane * 4));
            *(u32*)(th + off) = hi;
            *(u32*)(tl + off) = lo;
        }
    } else if (b < 800) {               // conv_h0 -> g_hbf[0]
        int idx = b - 736, chunk = idx & 15, mT = idx >> 4;
        char* th = (char*)&g_hbf[0][mT][chunk][0];
#pragma unroll
        for (int r = 0; r < 16; r++) {
            int m = r * 8 + w;
            const float2 v2 = *(const float2*)&enc[(size_t)(mT * 128 + m) * 1024 + chunk * 64 + lane * 2];
            u32 off = swz((u32)(m * 128 + lane * 4));
            *(u32*)(th + off) = pack2h(v2.x, v2.y);
        }
    } else if (b < 833) {               // flag init: t=0 preset to 2, rest 0
        int i = (b - 800) * 256 + tid;
        if (i < 129 * 64) ((u32*)g_flag)[i] = (i < 64) ? 2u : 0u;
    } else {                            // prep_bias: blocks 833..1344, warp per j
        int j = (b - 833) * 8 + w;
        float acc = 0.f;
#pragma unroll
        for (int i = 0; i < 8; i++) acc += Wih[(size_t)j * 256 + i * 32 + lane] * bout[i * 32 + lane];
#pragma unroll
        for (int o = 16; o; o >>= 1) acc += __shfl_xor_sync(0xFFFFFFFFu, acc, o);
        if (lane == 0) {
            float s = bih[j] + bhh[j];
            g_b0[j] = s;
            g_bf[j] = s + acc;
        }
    }
}

// ---------------- prep GEMM: g_wbf[1] = fp16(Whh + Wih @ Wout^T), bf16 3-pass -------
#define PREP_SMEM (128*1024 + 64*1024 + 1024)
__global__ __launch_bounds__(256, 1) void prep_mma(const float* __restrict__ Whh)
{
    extern __shared__ char smem[];
    u32 sb = (smem_u32(smem) + 1023) & ~1023u;
    int tid = threadIdx.x, lane = tid & 31, w = tid >> 5;
    int nT = blockIdx.x, kc = blockIdx.y;

    const char* srcA = (const char*)&g_pA[nT][0][0][0];
    const char* srcB = (const char*)&g_pB[kc][0][0][0];
#pragma unroll
    for (int r = 0; r < 32; r++) { int idx = r * 256 + tid; cpa16(sb + idx * 16, srcA + (size_t)idx * 16); }
#pragma unroll
    for (int r = 0; r < 16; r++) { int idx = r * 256 + tid; cpa16(sb + 131072 + idx * 16, srcB + (size_t)idx * 16); }
    CP_COMMIT(); CP_WAIT0();
    __syncthreads();

    int wm = w >> 1, wn = w & 1;
    const int aRow = ((lane >> 3) & 1) * 8 + (lane & 7);
    const int aKh  = lane >> 4;
    const int bRow = (lane >> 4) * 8 + (lane & 7);
    const int bKh  = (lane >> 3) & 1;

    float d[2][4][4] = {};
#pragma unroll
    for (int oc = 0; oc < 4; oc++) {
        u32 stA = sb + oc * 32768;
        u32 stB = sb + 131072 + oc * 16384;
#pragma unroll
        for (int k16 = 0; k16 < 4; k16++) {
            u32 aH[2][4], aL[2][4];
#pragma unroll
            for (int mi = 0; mi < 2; mi++) {
                u32 off = swz((u32)((wm * 32 + mi * 16 + aRow) * 128 + (k16 * 2 + aKh) * 16));
                ldsm4(aH[mi], stA + off);
                ldsm4(aL[mi], stA + 16384 + off);
            }
            u32 bH[2][4], bL[2][4];
#pragma unroll
            for (int bi = 0; bi < 2; bi++) {
                u32 off = swz((u32)((wn * 32 + bi * 16 + bRow) * 128 + (k16 * 2 + bKh) * 16));
                ldsm4(bH[bi], stB + off);
                ldsm4(bL[bi], stB + 8192 + off);
            }
#pragma unroll
            for (int mi = 0; mi < 2; mi++)
#pragma unroll
                for (int nj = 0; nj < 4; nj++) {
                    mma_bf16(d[mi][nj], aH[mi], &bH[nj >> 1][(nj & 1) * 2]);
                    mma_bf16(d[mi][nj], aH[mi], &bL[nj >> 1][(nj & 1) * 2]);
                    mma_bf16(d[mi][nj], aL[mi], &bH[nj >> 1][(nj & 1) * 2]);
                }
        }
    }

    char* th = (char*)&g_wbf[1][nT][kc][0];
#pragma unroll
    for (int mi = 0; mi < 2; mi++)
#pragma unroll
        for (int nj = 0; nj < 4; nj++)
#pragma unroll
            for (int rh = 0; rh < 2; rh++) {
                int n = wm * 32 + mi * 16 + (lane >> 2) + rh * 8;
                int j = rowj(nT, n);
                int k0l = wn * 32 + nj * 8 + 2 * (lane & 3);
                const float* wr = Whh + (size_t)j * 1024 + kc * 64 + k0l;
                u32 off = swz((u32)(n * 128 + k0l * 2));
                *(u32*)(th + off) = pack2h(d[mi][nj][rh * 2 + 0] + wr[0],
                                           d[mi][nj][rh * 2 + 1] + wr[1]);
            }
}

// ---------------- unified persistent kernel: 128 LSTM CTAs + 20 output workers -------
// LSTM smem: [mbars][Bres 8 chunks = 128KB][3 stages x 32KB]
#define BRES_CH 8
#define BRES_BYTES (BRES_CH*16384)
#define LSTAGE 32768
#define OSTG 32768
#define LSTM_SMEM (1024 + BRES_BYTES + 3*LSTAGE + 1024)
__global__ __launch_bounds__(256, 1) void persist(const float* __restrict__ bout,
                                                  float* __restrict__ out)
{
    extern __shared__ char smem[];
    u32 sb = (smem_u32(smem) + 1023) & ~1023u;
    const int tid = threadIdx.x, lane = tid & 31, w = tid >> 5;
    const int bid = blockIdx.x;
    const int wm = w >> 2, wn = w & 3;
    const int aRow = ((lane >> 3) & 1) * 8 + (lane & 7);
    const int aKh  = lane >> 4;
    const int bRow = (lane >> 4) * 8 + (lane & 7);
    const int bKh  = (lane >> 3) & 1;

    if (bid < 128) {
        // ================= LSTM role =================
        const int mT = bid >> 5, nT = bid & 31;
        const u32 mb = sb;                 // 3 chunk mbars at +0,+16,+32; preload mbar at +48
        const u32 mbP = sb + 48;
        const u32 sbBres  = sb + 1024;
        const u32 sbStage = sbBres + BRES_BYTES;

        if (tid == 0) {
            mbar_init(mb, 1);
            mbar_init(mb + 16, 1);
            mbar_init(mb + 32, 1);
            mbar_init(mbP, 1);
            asm volatile("fence.proxy.async.shared::cta;" ::: "memory");
        }
        __syncthreads();

        if (tid == 0) {
            const char* wres = (const char*)&g_wbf[1][nT][0];
            mbar_expect(mbP, BRES_BYTES);
#pragma unroll
            for (int c = 0; c < BRES_CH; c++)
                bulk_g2s(sbBres + c * 16384, wres + (size_t)c * 16384, 16384, mbP);

            // prologue: global chunks g=0,1,2 (t=1, stream B from Whh tiles)
            const char* B1 = (const char*)&g_wbf[0][nT][0];
            const char* A1 = (const char*)&g_hbf[0][mT][0];
#pragma unroll
            for (int i = 0; i < 3; i++) {
                u32 mbs = mb + 16 * i;
                mbar_expect(mbs, 32768);
                bulk_g2s(sbStage + i * LSTAGE, A1 + (size_t)i * 16384, 16384, mbs);
                bulk_g2s(sbStage + i * LSTAGE + 16384, B1 + (size_t)i * 16384, 16384, mbs);
            }
        }
        mbar_wait(mbP, 0);

        float bZ[2][4], bF[2][4];
#pragma unroll
        for (int cp = 0; cp < 2; cp++) {
            int cell = nT * 32 + wn * 8 + cp * 4 + (lane & 3);
#pragma unroll
            for (int g = 0; g < 4; g++) {
                bZ[cp][g] = g_b0[g * 1024 + cell];
                bF[cp][g] = g_bf[g * 1024 + cell];
            }
        }

        float creg[4][2][2];
#pragma unroll
        for (int mi = 0; mi < 4; mi++)
#pragma unroll
            for (int rh = 0; rh < 2; rh++)
#pragma unroll
                for (int cp = 0; cp < 2; cp++) creg[mi][rh][cp] = 0.f;

        for (int t = 1; t <= 128; t++) {
            const int first = (t == 1);
            const char* srcA = (const char*)&g_hbf[t - 1][mT][0];
            const char* srcB = first ? (const char*)&g_wbf[0][nT][0]
                                     : (const char*)&g_wbf[1][nT][0];
            const int gbase = (t - 1) * 16;

            float d[4][4][4];
#pragma unroll
            for (int mi = 0; mi < 4; mi++)
#pragma unroll
                for (int nj = 0; nj < 4; nj++)
#pragma unroll
                    for (int q = 0; q < 4; q++) d[mi][nj][q] = 0.f;

            for (int c = 0; c < 16; c++) {
                const int g = gbase + c;
                const int sg = g % 3;
                const u32 mbs = mb + 16 * sg;
                mbar_wait(mbs, (u32)((g / 3) & 1));
                u32 stA = sbStage + sg * LSTAGE;
                u32 stB = (!first && c < BRES_CH) ? (sbBres + c * 16384) : (stA + 16384);
#pragma unroll
                for (int k16 = 0; k16 < 4; k16++) {
                    u32 aH[4][4];
#pragma unroll
                    for (int mi = 0; mi < 4; mi++) {
                        u32 off = swz((u32)((wm * 64 + mi * 16 + aRow) * 128 + (k16 * 2 + aKh) * 16));
                        ldsm4(aH[mi], stA + off);
                    }
                    u32 bIFh[4], bGOh[4];
                    {
                        u32 offIF = swz((u32)((wn * 16 + bRow) * 128 + (k16 * 2 + bKh) * 16));
                        u32 offGO = swz((u32)((64 + wn * 16 + bRow) * 128 + (k16 * 2 + bKh) * 16));
                        ldsm4(bIFh, stB + offIF);
                        ldsm4(bGOh, stB + offGO);
                    }
#pragma unroll
                    for (int mi = 0; mi < 4; mi++)
#pragma unroll
                        for (int nj = 0; nj < 2; nj++) {
                            mma_f16(d[mi][nj],     aH[mi], &bIFh[nj * 2]);
                            mma_f16(d[mi][nj + 2], aH[mi], &bGOh[nj * 2]);
                        }
                }
                __syncthreads();   // all warps done with stage sg -> safe to refill
                if (tid == 0 && c + 3 < 16) {
                    int cn = c + 3;
                    if (!first) { flag_wait(&g_flag[t - 1][mT][cn]); FENCE_ACQ(); }
                    int bStream = (first || cn >= BRES_CH);
                    mbar_expect(mbs, bStream ? 32768u : 16384u);
                    bulk_g2s(stA, srcA + (size_t)cn * 16384, 16384, mbs);
                    if (bStream)
                        bulk_g2s(stA + 16384, srcB + (size_t)cn * 16384, 16384, mbs);
                }
            }

            // ---- epilogue: cell update (c in regs) + emit next A tile (hi-only) ----
            {
                const int chunk = nT >> 1;
                char* dh = (char*)&g_hbf[t][mT][chunk][0];
#pragma unroll
                for (int mi = 0; mi < 4; mi++)
#pragma unroll
                    for (int rh = 0; rh < 2; rh++) {
                        int bl = wm * 64 + mi * 16 + (lane >> 2) + rh * 8;
#pragma unroll
                        for (int cp = 0; cp < 2; cp++) {
                            int cl = wn * 8 + cp * 4 + (lane & 3);
                            float gi = d[mi][cp][rh * 2 + 0]     + (first ? bZ[cp][0] : bF[cp][0]);
                            float gf = d[mi][cp][rh * 2 + 1]     + (first ? bZ[cp][1] : bF[cp][1]);
                            float gg = d[mi][cp + 2][rh * 2 + 0] + (first ? bZ[cp][2] : bF[cp][2]);
                            float go = d[mi][cp + 2][rh * 2 + 1] + (first ? bZ[cp][3] : bF[cp][3]);
                            float cold = first ? 0.f : creg[mi][rh][cp];
                            float cn = sigm(gf) * cold + sigm(gi) * tanhf(gg);
                            float hn = sigm(go) * tanhf(cn);
                            creg[mi][rh][cp] = cn;
                            int kin = (nT & 1) * 32 + cl;
                            u32 off = swz((u32)(bl * 128 + kin * 2));
                            *(__half*)(dh + off) = __float2half_rn(hn);
                        }
                    }
            }

            __syncthreads();                 // all epilogue STGs issued
            if (tid == 0) {
                asm volatile("fence.release.gpu;" ::: "memory");
                asm volatile("red.relaxed.gpu.global.add.u32 [%0], %1;"
                             :: "l"(&g_flag[t][mT][nT >> 1]), "r"(1u) : "memory");
                if (t < 128) {
                    // refill chunks 0..2 of next step (A only; B resident for c<8)
                    flag_wait(&g_flag[t][mT][0]);
                    flag_wait(&g_flag[t][mT][1]);
                    flag_wait(&g_flag[t][mT][2]);
                    FENCE_ACQ();
                    const char* An = (const char*)&g_hbf[t][mT][0];
#pragma unroll
                    for (int i = 0; i < 3; i++) {
                        int g0 = t * 16 + i;
                        int sg = g0 % 3;
                        u32 mbs = mb + 16 * sg;
                        mbar_expect(mbs, 16384);
                        bulk_g2s(sbStage + sg * LSTAGE, An + (size_t)i * 16384, 16384, mbs);
                    }
                }
            }
            // no trailing __syncthreads: other threads block on next step's chunk mbars
        }
    } else {
        // ================= output worker role =================
        const int wk = bid - 128;   // 0..19
        const u32 mb0 = sb, mb1 = sb + 16;
        const u32 stg = sb + 1024;

        if (tid == 0) {
            mbar_init(mb0, 1);
            mbar_init(mb1, 1);
            asm volatile("fence.proxy.async.shared::cta;" ::: "memory");
        }
        __syncthreads();

        u32 ph0 = 0, ph1 = 0;

        for (int job = wk; job < 1024; job += 20) {
            const int t   = (job >> 3) + 1;       // h step 1..128
            const int mT  = job & 3;
            const int nOT = (job >> 2) & 1;

            const char* srcA = (const char*)&g_hbf[t][mT][0];       // 16KB/chunk
            const char* srcB = (const char*)&g_obf[nOT][0][0][0];   // hi at +0, 32KB stride

            if (tid == 0) {
                flag_wait(&g_flag[t][mT][0]);
                flag_wait(&g_flag[t][mT][1]);
                FENCE_ACQ();
                mbar_expect(mb0, 32768);
                bulk_g2s(stg, srcA, 16384, mb0);
                bulk_g2s(stg + 16384, srcB, 16384, mb0);
                mbar_expect(mb1, 32768);
                bulk_g2s(stg + OSTG, srcA + 16384, 16384, mb1);
                bulk_g2s(stg + OSTG + 16384, srcB + 32768, 16384, mb1);
            }

            float d[4][4][4];
#pragma unroll
            for (int mi = 0; mi < 4; mi++)
#pragma unroll
                for (int nj = 0; nj < 4; nj++)
#pragma unroll
                    for (int q = 0; q < 4; q++) d[mi][nj][q] = 0.f;

            for (int c = 0; c < 16; c++) {
                int s = c & 1;
                u32 mbs = s ? mb1 : mb0;
                if (s) { mbar_wait(mb1, ph1); ph1 ^= 1; }
                else   { mbar_wait(mb0, ph0); ph0 ^= 1; }
                u32 stA = stg + s * OSTG;
                u32 stB = stA + 16384;
#pragma unroll
                for (int k16 = 0; k16 < 4; k16++) {
                    u32 aH[4][4];
#pragma unroll
                    for (int mi = 0; mi < 4; mi++) {
                        u32 off = swz((u32)((wm * 64 + mi * 16 + aRow) * 128 + (k16 * 2 + aKh) * 16));
                        ldsm4(aH[mi], stA + off);
                    }
                    u32 bH[2][4];
#pragma unroll
                    for (int bi = 0; bi < 2; bi++) {
                        u32 off = swz((u32)((wn * 32 + bi * 16 + bRow) * 128 + (k16 * 2 + bKh) * 16));
                        ldsm4(bH[bi], stB + off);
                    }
#pragma unroll
                    for (int mi = 0; mi < 4; mi++)
#pragma unroll
                        for (int nj = 0; nj < 4; nj++)
                            mma_f16(d[mi][nj], aH[mi], &bH[nj >> 1][(nj & 1) * 2]);
                }
                __syncthreads();
                if (tid == 0 && c + 2 < 16) {
                    int cn = c + 2;
                    flag_wait(&g_flag[t][mT][cn]);
                    FENCE_ACQ();
                    mbar_expect(mbs, 32768);
                    bulk_g2s(stA, srcA + (size_t)cn * 16384, 16384, mbs);
                    bulk_g2s(stB, srcB + (size_t)cn * 32768, 16384, mbs);
                }
            }

#pragma unroll
            for (int mi = 0; mi < 4; mi++)
#pragma unroll
                for (int nj = 0; nj < 4; nj++)
#pragma unroll
                    for (int rh = 0; rh < 2; rh++) {
                        int bl = wm * 64 + mi * 16 + (lane >> 2) + rh * 8;
                        int b = mT * 128 + bl;
                        int o = nOT * 128 + wn * 32 + nj * 8 + 2 * (lane & 3);
                        float2 v = make_float2(d[mi][nj][rh * 2 + 0] + bout[o],
                                               d[mi][nj][rh * 2 + 1] + bout[o + 1]);
                        *(float2*)&out[(size_t)b * 32768 + (size_t)(t - 1) * 256 + o] = v;
                    }
        }
    }
}

// ---------------- launch ----------------
extern "C" void kernel_launch(void* const* d_in, const int* in_sizes, int n_in,
                              void* d_out, int out_size)
{
    const float *enc = nullptr, *Wih = nullptr, *Whh = nullptr;
    const float *bih = nullptr, *bhh = nullptr, *Wout = nullptr, *bout = nullptr;
    for (int i = 0; i < n_in; i++) {
        int s = in_sizes[i];
        if      (s == 512 * 1024)  enc  = (const float*)d_in[i];
        else if (s == 4096 * 256)  Wih  = (const float*)d_in[i];
        else if (s == 4096 * 1024) Whh  = (const float*)d_in[i];
        else if (s == 4096)        { if (!bih) bih = (const float*)d_in[i]; else bhh = (const float*)d_in[i]; }
        else if (s == 256 * 1024)  Wout = (const float*)d_in[i];
        else if (s == 256)         bout = (const float*)d_in[i];
    }
    if (!enc || !Wih || !Whh || !bih || !bhh || !Wout || !bout) return;

    cudaFuncSetAttribute(prep_mma, cudaFuncAttributeMaxDynamicSharedMemorySize, PREP_SMEM);
    cudaFuncSetAttribute(persist,  cudaFuncAttributeMaxDynamicSharedMemorySize, LSTM_SMEM);

    conv_all<<<1345, 256>>>(Whh, Wih, Wout, enc, bih, bhh, bout);
    prep_mma<<<dim3(32, 16), 256, PREP_SMEM>>>(Whh);
    persist<<<148, 256, LSTM_SMEM>>>(bout, (float*)d_out);
    (void)out_size;
}

// round 14
// speedup vs baseline: 1.1348x; 1.1348x over previous
#include <cuda_runtime.h>
#include <cuda_bf16.h>
#include <cuda_fp16.h>
#include <cstdint>

typedef unsigned long long ull;
typedef unsigned int u32;

// ---------------- scratch (static __device__, no allocations) ----------------
static __device__ float g_b0[4096];               // b_ih+b_hh
static __device__ float g_bf[4096];               // + W_ih@b_out
static __device__ u32   g_bar[516];               // per-(t,mT) arrival counters, t=1..128
// fp16 HI-ONLY weight tiles, gate-paired rows, SW128: [src][nT 32][chunk 16][128x64]
static __device__ __align__(256) __half g_wbf[2][32][16][8192];
// fp16 HI-ONLY hidden tiles: [t 0..128][mT 4][chunk 16][128x64]
static __device__ __align__(256) __half g_hbf[129][4][16][8192];
// fp16 output-weight tiles: [nOT 2][chunk 16][part 2][128x64] (hi at part 0)
static __device__ __align__(256) __half g_obf[2][16][2][8192];
// prep-GEMM operands (bf16 split, 3-pass prep path)
static __device__ __align__(256) __nv_bfloat16 g_pA[32][4][2][8192];
static __device__ __align__(256) __nv_bfloat16 g_pB[16][4][2][4096];

// ---------------- helpers ----------------
// fast sigmoid / tanh: MUFU ex2 + MUFU rcp, rel err ~1e-6, saturates correctly at ±inf
__device__ __forceinline__ float sigm(float x)  { return __fdividef(1.0f, 1.0f + __expf(-x)); }
__device__ __forceinline__ float ftanh(float x) { return __fdividef(2.0f, 1.0f + __expf(-2.0f * x)) - 1.0f; }
__device__ __forceinline__ u32 swz(u32 x) { return x ^ ((x >> 3) & 0x70); }
__device__ __forceinline__ u32 smem_u32(const void* p) {
    u32 a; asm("{ .reg .u64 t; cvta.to.shared.u64 t, %1; cvt.u32.u64 %0, t; }" : "=r"(a) : "l"(p));
    return a;
}
__device__ __forceinline__ void cpa16(u32 dst, const void* src) {
    asm volatile("cp.async.cg.shared.global [%0], [%1], 16;" :: "r"(dst), "l"(src));
}
#define CP_COMMIT() asm volatile("cp.async.commit_group;" ::: "memory")
#define CP_WAIT0()  asm volatile("cp.async.wait_group 0;" ::: "memory")

// ---- bulk copy + mbarrier ----
__device__ __forceinline__ void bulk_g2s(u32 dst, const void* src, u32 bytes, u32 mbar) {
    asm volatile("cp.async.bulk.shared::cta.global.mbarrier::complete_tx::bytes [%0], [%1], %2, [%3];"
                 :: "r"(dst), "l"(src), "r"(bytes), "r"(mbar) : "memory");
}
__device__ __forceinline__ void mbar_init(u32 a, u32 cnt) {
    asm volatile("mbarrier.init.shared.b64 [%0], %1;" :: "r"(a), "r"(cnt) : "memory");
}
__device__ __forceinline__ void mbar_expect(u32 a, u32 tx) {
    asm volatile("mbarrier.arrive.expect_tx.shared.b64 _, [%0], %1;" :: "r"(a), "r"(tx) : "memory");
}
__device__ __forceinline__ void mbar_wait(u32 a, u32 ph) {
    asm volatile("{\n\t.reg .pred P;\n\t"
                 "WL_%=:\n\t"
                 "mbarrier.try_wait.parity.acquire.cta.shared::cta.b64 P, [%0], %1, 0x989680;\n\t"
                 "@P bra.uni WD_%=;\n\t"
                 "bra.uni WL_%=;\n\t"
                 "WD_%=:\n\t}"
                 :: "r"(a), "r"(ph) : "memory");
}

__device__ __forceinline__ void ldsm4(u32* r, u32 addr) {
    asm volatile("ldmatrix.sync.aligned.m8n8.x4.shared.b16 {%0,%1,%2,%3}, [%4];"
                 : "=r"(r[0]), "=r"(r[1]), "=r"(r[2]), "=r"(r[3]) : "r"(addr));
}
__device__ __forceinline__ void mma_bf16(float* d, const u32* a, const u32* b) {
    asm volatile("mma.sync.aligned.m16n8k16.row.col.f32.bf16.bf16.f32 "
                 "{%0,%1,%2,%3}, {%4,%5,%6,%7}, {%8,%9}, {%0,%1,%2,%3};"
                 : "+f"(d[0]), "+f"(d[1]), "+f"(d[2]), "+f"(d[3])
                 : "r"(a[0]), "r"(a[1]), "r"(a[2]), "r"(a[3]), "r"(b[0]), "r"(b[1]));
}
__device__ __forceinline__ void mma_f16(float* d, const u32* a, const u32* b) {
    asm volatile("mma.sync.aligned.m16n8k16.row.col.f32.f16.f16.f32 "
                 "{%0,%1,%2,%3}, {%4,%5,%6,%7}, {%8,%9}, {%0,%1,%2,%3};"
                 : "+f"(d[0]), "+f"(d[1]), "+f"(d[2]), "+f"(d[3])
                 : "r"(a[0]), "r"(a[1]), "r"(a[2]), "r"(a[3]), "r"(b[0]), "r"(b[1]));
}
__device__ __forceinline__ void split_h16(float v, __half& h, __half& l) {
    h = __float2half_rn(v);
    l = __float2half_rn(v - __half2float(h));
}
__device__ __forceinline__ u32 pack2h(float v0, float v1) {
    __half h0 = __float2half_rn(v0), h1 = __float2half_rn(v1);
    return (u32)__half_as_ushort(h0) | ((u32)__half_as_ushort(h1) << 16);
}
__device__ __forceinline__ u32 pack_split2h(float v0, float v1, u32& lo_out) {
    __half h0, l0, h1, l1;
    split_h16(v0, h0, l0); split_h16(v1, h1, l1);
    lo_out = (u32)__half_as_ushort(l0) | ((u32)__half_as_ushort(l1) << 16);
    return (u32)__half_as_ushort(h0) | ((u32)__half_as_ushort(h1) << 16);
}
__device__ __forceinline__ void split_bf(float v, __nv_bfloat16& h, __nv_bfloat16& l) {
    h = __float2bfloat16(v);
    l = __float2bfloat16(v - __bfloat162float(h));
}
// gate-paired row -> j (j = gate*1024 + cell)
__device__ __forceinline__ int rowj(int nT, int n) {
    int half = n >> 6, m = n & 63;
    return (half * 2 + (m & 1)) * 1024 + nT * 32 + (m >> 1);
}

// ---------------- merged prep: convs + bias + flag init, one launch ----------------
__global__ void conv_all(const float* __restrict__ Whh, const float* __restrict__ Wih,
                         const float* __restrict__ Wout, const float* __restrict__ enc,
                         const float* __restrict__ bih, const float* __restrict__ bhh,
                         const float* __restrict__ bout)
{
    int b = blockIdx.x;
    int tid = threadIdx.x, w = tid >> 5, lane = tid & 31;

    if (b < 512) {                      // conv_w0: Whh -> g_wbf[0]
        int chunk = b & 15, nT = b >> 4;
        char* th = (char*)&g_wbf[0][nT][chunk][0];
#pragma unroll
        for (int r = 0; r < 16; r++) {
            int n = r * 8 + w;
            const float2 v2 = *(const float2*)&Whh[(size_t)rowj(nT, n) * 1024 + chunk * 64 + lane * 2];
            u32 off = swz((u32)(n * 128 + lane * 4));
            *(u32*)(th + off) = pack2h(v2.x, v2.y);
        }
    } else if (b < 640) {               // conv_wih -> g_pA (bf16 split)
        int idx = b - 512, oc = idx & 3, nT = idx >> 2;
        char* th = (char*)&g_pA[nT][oc][0][0];
        char* tl = th + 16384;
#pragma unroll
        for (int r = 0; r < 16; r++) {
            int n = r * 8 + w;
            const float2 v2 = *(const float2*)&Wih[(size_t)rowj(nT, n) * 256 + oc * 64 + lane * 2];
            __nv_bfloat16 h0, l0, h1, l1;
            split_bf(v2.x, h0, l0); split_bf(v2.y, h1, l1);
            u32 hi = (u32)__bfloat16_as_ushort(h0) | ((u32)__bfloat16_as_ushort(h1) << 16);
            u32 lo = (u32)__bfloat16_as_ushort(l0) | ((u32)__bfloat16_as_ushort(l1) << 16);
            u32 off = swz((u32)(n * 128 + lane * 4));
            *(u32*)(th + off) = hi;
            *(u32*)(tl + off) = lo;
        }
    } else if (b < 704) {               // conv_woutT -> g_pB (bf16 split)
        int idx = b - 640, oc = idx & 3, kc = idx >> 2;
        int k = tid & 63, og = tid >> 6;
        char* th = (char*)&g_pB[kc][oc][0][0];
        char* tl = th + 8192;
#pragma unroll
        for (int i = 0; i < 16; i++) {
            int oo = og * 16 + i;
            float v = Wout[(size_t)(oc * 64 + oo) * 1024 + kc * 64 + k];
            __nv_bfloat16 h, l; split_bf(v, h, l);
            u32 off = swz((u32)(k * 128 + oo * 2));
            *(__nv_bfloat16*)(th + off) = h;
            *(__nv_bfloat16*)(tl + off) = l;
        }
    } else if (b < 736) {               // conv_obf -> g_obf (fp16 split; hi used)
        int idx = b - 704, chunk = idx & 15, nOT = idx >> 4;
        char* th = (char*)&g_obf[nOT][chunk][0][0];
        char* tl = th + 16384;
#pragma unroll
        for (int r = 0; r < 16; r++) {
            int n = r * 8 + w;
            const float2 v2 = *(const float2*)&Wout[(size_t)(nOT * 128 + n) * 1024 + chunk * 64 + lane * 2];
            u32 lo, hi = pack_split2h(v2.x, v2.y, lo);
            u32 off = swz((u32)(n * 128 + lane * 4));
            *(u32*)(th + off) = hi;
            *(u32*)(tl + off) = lo;
        }
    } else if (b < 800) {               // conv_h0 -> g_hbf[0]
        int idx = b - 736, chunk = idx & 15, mT = idx >> 4;
        char* th = (char*)&g_hbf[0][mT][chunk][0];
#pragma unroll
        for (int r = 0; r < 16; r++) {
            int m = r * 8 + w;
            const float2 v2 = *(const float2*)&enc[(size_t)(mT * 128 + m) * 1024 + chunk * 64 + lane * 2];
            u32 off = swz((u32)(m * 128 + lane * 4));
            *(u32*)(th + off) = pack2h(v2.x, v2.y);
        }
    } else if (b < 804) {               // flag init
        int i = (b - 800) * 256 + tid;
        if (i < 516) g_bar[i] = 0;
    } else {                            // prep_bias: blocks 804..1315, warp per j
        int j = (b - 804) * 8 + w;
        float acc = 0.f;
#pragma unroll
        for (int i = 0; i < 8; i++) acc += Wih[(size_t)j * 256 + i * 32 + lane] * bout[i * 32 + lane];
#pragma unroll
        for (int o = 16; o; o >>= 1) acc += __shfl_xor_sync(0xFFFFFFFFu, acc, o);
        if (lane == 0) {
            float s = bih[j] + bhh[j];
            g_b0[j] = s;
            g_bf[j] = s + acc;
        }
    }
}

// ---------------- prep GEMM: g_wbf[1] = fp16(Whh + Wih @ Wout^T), bf16 3-pass -------
#define PREP_SMEM (128*1024 + 64*1024 + 1024)
__global__ __launch_bounds__(256, 1) void prep_mma(const float* __restrict__ Whh)
{
    extern __shared__ char smem[];
    u32 sb = (smem_u32(smem) + 1023) & ~1023u;
    int tid = threadIdx.x, lane = tid & 31, w = tid >> 5;
    int nT = blockIdx.x, kc = blockIdx.y;

    const char* srcA = (const char*)&g_pA[nT][0][0][0];
    const char* srcB = (const char*)&g_pB[kc][0][0][0];
#pragma unroll
    for (int r = 0; r < 32; r++) { int idx = r * 256 + tid; cpa16(sb + idx * 16, srcA + (size_t)idx * 16); }
#pragma unroll
    for (int r = 0; r < 16; r++) { int idx = r * 256 + tid; cpa16(sb + 131072 + idx * 16, srcB + (size_t)idx * 16); }
    CP_COMMIT(); CP_WAIT0();
    __syncthreads();

    int wm = w >> 1, wn = w & 1;
    const int aRow = ((lane >> 3) & 1) * 8 + (lane & 7);
    const int aKh  = lane >> 4;
    const int bRow = (lane >> 4) * 8 + (lane & 7);
    const int bKh  = (lane >> 3) & 1;

    float d[2][4][4] = {};
#pragma unroll
    for (int oc = 0; oc < 4; oc++) {
        u32 stA = sb + oc * 32768;
        u32 stB = sb + 131072 + oc * 16384;
#pragma unroll
        for (int k16 = 0; k16 < 4; k16++) {
            u32 aH[2][4], aL[2][4];
#pragma unroll
            for (int mi = 0; mi < 2; mi++) {
                u32 off = swz((u32)((wm * 32 + mi * 16 + aRow) * 128 + (k16 * 2 + aKh) * 16));
                ldsm4(aH[mi], stA + off);
                ldsm4(aL[mi], stA + 16384 + off);
            }
            u32 bH[2][4], bL[2][4];
#pragma unroll
            for (int bi = 0; bi < 2; bi++) {
                u32 off = swz((u32)((wn * 32 + bi * 16 + bRow) * 128 + (k16 * 2 + bKh) * 16));
                ldsm4(bH[bi], stB + off);
                ldsm4(bL[bi], stB + 8192 + off);
            }
#pragma unroll
            for (int mi = 0; mi < 2; mi++)
#pragma unroll
                for (int nj = 0; nj < 4; nj++) {
                    mma_bf16(d[mi][nj], aH[mi], &bH[nj >> 1][(nj & 1) * 2]);
                    mma_bf16(d[mi][nj], aH[mi], &bL[nj >> 1][(nj & 1) * 2]);
                    mma_bf16(d[mi][nj], aL[mi], &bH[nj >> 1][(nj & 1) * 2]);
                }
        }
    }

    char* th = (char*)&g_wbf[1][nT][kc][0];
#pragma unroll
    for (int mi = 0; mi < 2; mi++)
#pragma unroll
        for (int nj = 0; nj < 4; nj++)
#pragma unroll
            for (int rh = 0; rh < 2; rh++) {
                int n = wm * 32 + mi * 16 + (lane >> 2) + rh * 8;
                int j = rowj(nT, n);
                int k0l = wn * 32 + nj * 8 + 2 * (lane & 3);
                const float* wr = Whh + (size_t)j * 1024 + kc * 64 + k0l;
                u32 off = swz((u32)(n * 128 + k0l * 2));
                *(u32*)(th + off) = pack2h(d[mi][nj][rh * 2 + 0] + wr[0],
                                           d[mi][nj][rh * 2 + 1] + wr[1]);
            }
}

// ---------------- unified persistent kernel: 128 LSTM CTAs + 20 output workers -------
#define BRES_BYTES 163840
#define LSTAGE 32768
#define OSTG 32768
#define LSTM_SMEM (1024 + 1024 + BRES_BYTES + 2*LSTAGE)
__global__ __launch_bounds__(256, 1) void persist(const float* __restrict__ bout,
                                                  float* __restrict__ out)
{
    extern __shared__ char smem[];
    u32 sb = (smem_u32(smem) + 1023) & ~1023u;
    const int tid = threadIdx.x, lane = tid & 31, w = tid >> 5;
    const int bid = blockIdx.x;
    const int wm = w >> 2, wn = w & 3;
    const int aRow = ((lane >> 3) & 1) * 8 + (lane & 7);
    const int aKh  = lane >> 4;
    const int bRow = (lane >> 4) * 8 + (lane & 7);
    const int bKh  = (lane >> 3) & 1;

    if (bid < 128) {
        // ================= LSTM role =================
        const int mT = bid >> 5, nT = bid & 31;
        const u32 mb0 = sb, mb1 = sb + 16, mbP = sb + 32;
        const u32 sbBres  = sb + 1024;
        const u32 sbStage = sbBres + BRES_BYTES;

        if (tid == 0) {
            mbar_init(mb0, 1);
            mbar_init(mb1, 1);
            mbar_init(mbP, 1);
            asm volatile("fence.proxy.async.shared::cta;" ::: "memory");
        }
        __syncthreads();

        if (tid == 0) {
            const char* wres = (const char*)&g_wbf[1][nT][0];
            mbar_expect(mbP, BRES_BYTES);
#pragma unroll
            for (int c = 0; c < 10; c++)
                bulk_g2s(sbBres + c * 16384, wres + (size_t)c * 16384, 16384, mbP);

            const char* B1 = (const char*)&g_wbf[0][nT][0];
            const char* A1 = (const char*)&g_hbf[0][mT][0];
            mbar_expect(mb0, 32768);
            bulk_g2s(sbStage, A1, 16384, mb0);
            bulk_g2s(sbStage + 16384, B1, 16384, mb0);
            mbar_expect(mb1, 32768);
            bulk_g2s(sbStage + LSTAGE, A1 + 16384, 16384, mb1);
            bulk_g2s(sbStage + LSTAGE + 16384, B1 + 16384, 16384, mb1);
        }
        mbar_wait(mbP, 0);

        float bZ[2][4], bF[2][4];
#pragma unroll
        for (int cp = 0; cp < 2; cp++) {
            int cell = nT * 32 + wn * 8 + cp * 4 + (lane & 3);
#pragma unroll
            for (int g = 0; g < 4; g++) {
                bZ[cp][g] = g_b0[g * 1024 + cell];
                bF[cp][g] = g_bf[g * 1024 + cell];
            }
        }

        float creg[4][2][2];
#pragma unroll
        for (int mi = 0; mi < 4; mi++)
#pragma unroll
            for (int rh = 0; rh < 2; rh++)
#pragma unroll
                for (int cp = 0; cp < 2; cp++) creg[mi][rh][cp] = 0.f;

        u32 ph0 = 0, ph1 = 0;

        for (int t = 1; t <= 128; t++) {
            const int first = (t == 1);
            const char* srcA = (const char*)&g_hbf[t - 1][mT][0];
            const char* srcB = first ? (const char*)&g_wbf[0][nT][0]
                                     : (const char*)&g_wbf[1][nT][0];

            float d[4][4][4];
#pragma unroll
            for (int mi = 0; mi < 4; mi++)
#pragma unroll
                for (int nj = 0; nj < 4; nj++)
#pragma unroll
                    for (int q = 0; q < 4; q++) d[mi][nj][q] = 0.f;

            for (int c = 0; c < 16; c++) {
                int s = c & 1;
                u32 mbs = s ? mb1 : mb0;
                if (s) { mbar_wait(mb1, ph1); ph1 ^= 1; }
                else   { mbar_wait(mb0, ph0); ph0 ^= 1; }
                u32 stA = sbStage + s * LSTAGE;
                u32 stB = (!first && c < 10) ? (sbBres + c * 16384) : (stA + 16384);
#pragma unroll
                for (int k16 = 0; k16 < 4; k16++) {
                    u32 aH[4][4];
#pragma unroll
                    for (int mi = 0; mi < 4; mi++) {
                        u32 off = swz((u32)((wm * 64 + mi * 16 + aRow) * 128 + (k16 * 2 + aKh) * 16));
                        ldsm4(aH[mi], stA + off);
                    }
                    u32 bIFh[4], bGOh[4];
                    {
                        u32 offIF = swz((u32)((wn * 16 + bRow) * 128 + (k16 * 2 + bKh) * 16));
                        u32 offGO = swz((u32)((64 + wn * 16 + bRow) * 128 + (k16 * 2 + bKh) * 16));
                        ldsm4(bIFh, stB + offIF);
                        ldsm4(bGOh, stB + offGO);
                    }
#pragma unroll
                    for (int mi = 0; mi < 4; mi++)
#pragma unroll
                        for (int nj = 0; nj < 2; nj++) {
                            mma_f16(d[mi][nj],     aH[mi], &bIFh[nj * 2]);
                            mma_f16(d[mi][nj + 2], aH[mi], &bGOh[nj * 2]);
                        }
                }
                __syncthreads();   // all warps done with stage s -> safe to refill
                if (tid == 0 && c + 2 < 16) {
                    int cn = c + 2;
                    int bStream = (first || cn >= 10);
                    mbar_expect(mbs, bStream ? 32768u : 16384u);
                    bulk_g2s(stA, srcA + (size_t)cn * 16384, 16384, mbs);
                    if (bStream)
                        bulk_g2s(stA + 16384, srcB + (size_t)cn * 16384, 16384, mbs);
                }
            }

            // ---- epilogue: cell update (c in regs, fast nonlinearities) ----
            {
                const int chunk = nT >> 1;
                char* dh = (char*)&g_hbf[t][mT][chunk][0];
#pragma unroll
                for (int mi = 0; mi < 4; mi++)
#pragma unroll
                    for (int rh = 0; rh < 2; rh++) {
                        int bl = wm * 64 + mi * 16 + (lane >> 2) + rh * 8;
#pragma unroll
                        for (int cp = 0; cp < 2; cp++) {
                            int cl = wn * 8 + cp * 4 + (lane & 3);
                            float gi = d[mi][cp][rh * 2 + 0]     + (first ? bZ[cp][0] : bF[cp][0]);
                            float gf = d[mi][cp][rh * 2 + 1]     + (first ? bZ[cp][1] : bF[cp][1]);
                            float gg = d[mi][cp + 2][rh * 2 + 0] + (first ? bZ[cp][2] : bF[cp][2]);
                            float go = d[mi][cp + 2][rh * 2 + 1] + (first ? bZ[cp][3] : bF[cp][3]);
                            float cold = first ? 0.f : creg[mi][rh][cp];
                            float cn = sigm(gf) * cold + sigm(gi) * ftanh(gg);
                            float hn = sigm(go) * ftanh(cn);
                            creg[mi][rh][cp] = cn;
                            int kin = (nT & 1) * 32 + cl;
                            u32 off = swz((u32)(bl * 128 + kin * 2));
                            *(__half*)(dh + off) = __float2half_rn(hn);
                        }
                    }
            }

            __syncthreads();                 // all epilogue STGs issued
            if (tid == 0) {
                u32* bp = &g_bar[t * 4 + mT];
                asm volatile("red.release.gpu.global.add.u32 [%0], %1;" :: "l"(bp), "r"(1u) : "memory");
                if (t < 128) {
                    u32 v;
                    asm volatile("ld.relaxed.gpu.global.u32 %0, [%1];" : "=r"(v) : "l"(bp) : "memory");
                    while (v < 32) {
                        asm volatile("nanosleep.u32 32;");
                        asm volatile("ld.relaxed.gpu.global.u32 %0, [%1];" : "=r"(v) : "l"(bp) : "memory");
                    }
                    asm volatile("fence.acquire.gpu;" ::: "memory");
                    const char* An = (const char*)&g_hbf[t][mT][0];
                    mbar_expect(mb0, 16384);
                    bulk_g2s(sbStage, An, 16384, mb0);
                    mbar_expect(mb1, 16384);
                    bulk_g2s(sbStage + LSTAGE, An + 16384, 16384, mb1);
                }
            }
            if (t < 128) __syncthreads();
        }
    } else {
        // ================= output worker role =================
        const int wk = bid - 128;   // 0..19
        const u32 mb0 = sb, mb1 = sb + 16;
        const u32 stg = sb + 1024;

        if (tid == 0) {
            mbar_init(mb0, 1);
            mbar_init(mb1, 1);
            asm volatile("fence.proxy.async.shared::cta;" ::: "memory");
        }
        __syncthreads();

        u32 ph0 = 0, ph1 = 0;

        for (int job = wk; job < 1024; job += 20) {
            const int t   = (job >> 3) + 1;       // h step 1..128
            const int mT  = job & 3;
            const int nOT = (job >> 2) & 1;

            if (tid == 0) {
                const u32* bp = &g_bar[t * 4 + mT];
                u32 v;
                asm volatile("ld.relaxed.gpu.global.u32 %0, [%1];" : "=r"(v) : "l"(bp) : "memory");
                while (v < 32) {
                    asm volatile("nanosleep.u32 64;");
                    asm volatile("ld.relaxed.gpu.global.u32 %0, [%1];" : "=r"(v) : "l"(bp) : "memory");
                }
                asm volatile("fence.acquire.gpu;" ::: "memory");
            }
            __syncthreads();

            const char* srcA = (const char*)&g_hbf[t][mT][0];       // 16KB/chunk
            const char* srcB = (const char*)&g_obf[nOT][0][0][0];   // hi at +0, 32KB stride

            if (tid == 0) {
                mbar_expect(mb0, 32768);
                bulk_g2s(stg, srcA, 16384, mb0);
                bulk_g2s(stg + 16384, srcB, 16384, mb0);
                mbar_expect(mb1, 32768);
                bulk_g2s(stg + OSTG, srcA + 16384, 16384, mb1);
                bulk_g2s(stg + OSTG + 16384, srcB + 32768, 16384, mb1);
            }

            float d[4][4][4];
#pragma unroll
            for (int mi = 0; mi < 4; mi++)
#pragma unroll
                for (int nj = 0; nj < 4; nj++)
#pragma unroll
                    for (int q = 0; q < 4; q++) d[mi][nj][q] = 0.f;

            for (int c = 0; c < 16; c++) {
                int s = c & 1;
                u32 mbs = s ? mb1 : mb0;
                if (s) { mbar_wait(mb1, ph1); ph1 ^= 1; }
                else   { mbar_wait(mb0, ph0); ph0 ^= 1; }
                u32 stA = stg + s * OSTG;
                u32 stB = stA + 16384;
#pragma unroll
                for (int k16 = 0; k16 < 4; k16++) {
                    u32 aH[4][4];
#pragma unroll
                    for (int mi = 0; mi < 4; mi++) {
                        u32 off = swz((u32)((wm * 64 + mi * 16 + aRow) * 128 + (k16 * 2 + aKh) * 16));
                        ldsm4(aH[mi], stA + off);
                    }
                    u32 bH[2][4];
#pragma unroll
                    for (int bi = 0; bi < 2; bi++) {
                        u32 off = swz((u32)((wn * 32 + bi * 16 + bRow) * 128 + (k16 * 2 + bKh) * 16));
                        ldsm4(bH[bi], stB + off);
                    }
#pragma unroll
                    for (int mi = 0; mi < 4; mi++)
#pragma unroll
                        for (int nj = 0; nj < 4; nj++)
                            mma_f16(d[mi][nj], aH[mi], &bH[nj >> 1][(nj & 1) * 2]);
                }
                __syncthreads();
                if (tid == 0 && c + 2 < 16) {
                    int cn = c + 2;
                    mbar_expect(mbs, 32768);
                    bulk_g2s(stA, srcA + (size_t)cn * 16384, 16384, mbs);
                    bulk_g2s(stB, srcB + (size_t)cn * 32768, 16384, mbs);
                }
            }

#pragma unroll
            for (int mi = 0; mi < 4; mi++)
#pragma unroll
                for (int nj = 0; nj < 4; nj++)
#pragma unroll
                    for (int rh = 0; rh < 2; rh++) {
                        int bl = wm * 64 + mi * 16 + (lane >> 2) + rh * 8;
                        int b = mT * 128 + bl;
                        int o = nOT * 128 + wn * 32 + nj * 8 + 2 * (lane & 3);
                        float2 v = make_float2(d[mi][nj][rh * 2 + 0] + bout[o],
                                               d[mi][nj][rh * 2 + 1] + bout[o + 1]);
                        *(float2*)&out[(size_t)b * 32768 + (size_t)(t - 1) * 256 + o] = v;
                    }
        }
    }
}

// ---------------- launch ----------------
extern "C" void kernel_launch(void* const* d_in, const int* in_sizes, int n_in,
                              void* d_out, int out_size)
{
    const float *enc = nullptr, *Wih = nullptr, *Whh = nullptr;
    const float *bih = nullptr, *bhh = nullptr, *Wout = nullptr, *bout = nullptr;
    for (int i = 0; i < n_in; i++) {
        int s = in_sizes[i];
        if      (s == 512 * 1024)  enc  = (const float*)d_in[i];
        else if (s == 4096 * 256)  Wih  = (const float*)d_in[i];
        else if (s == 4096 * 1024) Whh  = (const float*)d_in[i];
        else if (s == 4096)        { if (!bih) bih = (const float*)d_in[i]; else bhh = (const float*)d_in[i]; }
        else if (s == 256 * 1024)  Wout = (const float*)d_in[i];
        else if (s == 256)         bout = (const float*)d_in[i];
    }
    if (!enc || !Wih || !Whh || !bih || !bhh || !Wout || !bout) return;

    cudaFuncSetAttribute(prep_mma, cudaFuncAttributeMaxDynamicSharedMemorySize, PREP_SMEM);
    cudaFuncSetAttribute(persist,  cudaFuncAttributeMaxDynamicSharedMemorySize, LSTM_SMEM);

    conv_all<<<1316, 256>>>(Whh, Wih, Wout, enc, bih, bhh, bout);
    prep_mma<<<dim3(32, 16), 256, PREP_SMEM>>>(Whh);
    persist<<<148, 256, LSTM_SMEM>>>(bout, (float*)d_out);
    (void)out_size;
}

// round 15
// speedup vs baseline: 1.1378x; 1.0027x over previous
#include <cuda_runtime.h>
#include <cuda_bf16.h>
#include <cuda_fp16.h>
#include <cstdint>

typedef unsigned long long ull;
typedef unsigned int u32;

// ---------------- scratch (static __device__, no allocations) ----------------
static __device__ float g_b0[4096];               // b_ih+b_hh
static __device__ float g_bf[4096];               // + W_ih@b_out
static __device__ u32   g_bar[516];               // per-(t,mT) full counters (target 32)
static __device__ u32   g_bc[129][4][4];          // per-(t,mT,chunk 0..2) counters (target 2)
// fp16 HI-ONLY weight tiles, gate-paired rows, SW128: [src][nT 32][chunk 16][128x64]
static __device__ __align__(256) __half g_wbf[2][32][16][8192];
// fp16 HI-ONLY hidden tiles: [t 0..128][mT 4][chunk 16][128x64]
static __device__ __align__(256) __half g_hbf[129][4][16][8192];
// fp16 output-weight tiles: [nOT 2][chunk 16][part 2][128x64] (hi at part 0)
static __device__ __align__(256) __half g_obf[2][16][2][8192];
// prep-GEMM operands (bf16 split, 3-pass prep path)
static __device__ __align__(256) __nv_bfloat16 g_pA[32][4][2][8192];
static __device__ __align__(256) __nv_bfloat16 g_pB[16][4][2][4096];

// ---------------- helpers ----------------
__device__ __forceinline__ float sigm(float x)  { return __fdividef(1.0f, 1.0f + __expf(-x)); }
__device__ __forceinline__ float ftanh(float x) { return __fdividef(2.0f, 1.0f + __expf(-2.0f * x)) - 1.0f; }
__device__ __forceinline__ u32 swz(u32 x) { return x ^ ((x >> 3) & 0x70); }
__device__ __forceinline__ u32 smem_u32(const void* p) {
    u32 a; asm("{ .reg .u64 t; cvta.to.shared.u64 t, %1; cvt.u32.u64 %0, t; }" : "=r"(a) : "l"(p));
    return a;
}
__device__ __forceinline__ void cpa16(u32 dst, const void* src) {
    asm volatile("cp.async.cg.shared.global [%0], [%1], 16;" :: "r"(dst), "l"(src));
}
#define CP_COMMIT() asm volatile("cp.async.commit_group;" ::: "memory")
#define CP_WAIT0()  asm volatile("cp.async.wait_group 0;" ::: "memory")

// ---- bulk copy + mbarrier ----
__device__ __forceinline__ void bulk_g2s(u32 dst, const void* src, u32 bytes, u32 mbar) {
    asm volatile("cp.async.bulk.shared::cta.global.mbarrier::complete_tx::bytes [%0], [%1], %2, [%3];"
                 :: "r"(dst), "l"(src), "r"(bytes), "r"(mbar) : "memory");
}
__device__ __forceinline__ void mbar_init(u32 a, u32 cnt) {
    asm volatile("mbarrier.init.shared.b64 [%0], %1;" :: "r"(a), "r"(cnt) : "memory");
}
__device__ __forceinline__ void mbar_expect(u32 a, u32 tx) {
    asm volatile("mbarrier.arrive.expect_tx.shared.b64 _, [%0], %1;" :: "r"(a), "r"(tx) : "memory");
}
__device__ __forceinline__ void mbar_wait(u32 a, u32 ph) {
    asm volatile("{\n\t.reg .pred P;\n\t"
                 "WL_%=:\n\t"
                 "mbarrier.try_wait.parity.acquire.cta.shared::cta.b64 P, [%0], %1, 0x989680;\n\t"
                 "@P bra.uni WD_%=;\n\t"
                 "bra.uni WL_%=;\n\t"
                 "WD_%=:\n\t}"
                 :: "r"(a), "r"(ph) : "memory");
}
// tid0-only relaxed poll; caller issues fence.acquire.gpu after
__device__ __forceinline__ void flag_wait(const u32* p, u32 tgt) {
    u32 v;
    asm volatile("ld.relaxed.gpu.global.u32 %0, [%1];" : "=r"(v) : "l"(p) : "memory");
    while (v < tgt) {
        asm volatile("nanosleep.u32 16;");
        asm volatile("ld.relaxed.gpu.global.u32 %0, [%1];" : "=r"(v) : "l"(p) : "memory");
    }
}
#define FENCE_ACQ() asm volatile("fence.acquire.gpu;" ::: "memory")
__device__ __forceinline__ void rel_add(u32* p) {
    asm volatile("red.release.gpu.global.add.u32 [%0], %1;" :: "l"(p), "r"(1u) : "memory");
}

__device__ __forceinline__ void ldsm4(u32* r, u32 addr) {
    asm volatile("ldmatrix.sync.aligned.m8n8.x4.shared.b16 {%0,%1,%2,%3}, [%4];"
                 : "=r"(r[0]), "=r"(r[1]), "=r"(r[2]), "=r"(r[3]) : "r"(addr));
}
__device__ __forceinline__ void mma_bf16(float* d, const u32* a, const u32* b) {
    asm volatile("mma.sync.aligned.m16n8k16.row.col.f32.bf16.bf16.f32 "
                 "{%0,%1,%2,%3}, {%4,%5,%6,%7}, {%8,%9}, {%0,%1,%2,%3};"
                 : "+f"(d[0]), "+f"(d[1]), "+f"(d[2]), "+f"(d[3])
                 : "r"(a[0]), "r"(a[1]), "r"(a[2]), "r"(a[3]), "r"(b[0]), "r"(b[1]));
}
__device__ __forceinline__ void mma_f16(float* d, const u32* a, const u32* b) {
    asm volatile("mma.sync.aligned.m16n8k16.row.col.f32.f16.f16.f32 "
                 "{%0,%1,%2,%3}, {%4,%5,%6,%7}, {%8,%9}, {%0,%1,%2,%3};"
                 : "+f"(d[0]), "+f"(d[1]), "+f"(d[2]), "+f"(d[3])
                 : "r"(a[0]), "r"(a[1]), "r"(a[2]), "r"(a[3]), "r"(b[0]), "r"(b[1]));
}
__device__ __forceinline__ void split_h16(float v, __half& h, __half& l) {
    h = __float2half_rn(v);
    l = __float2half_rn(v - __half2float(h));
}
__device__ __forceinline__ u32 pack2h(float v0, float v1) {
    __half h0 = __float2half_rn(v0), h1 = __float2half_rn(v1);
    return (u32)__half_as_ushort(h0) | ((u32)__half_as_ushort(h1) << 16);
}
__device__ __forceinline__ u32 pack_split2h(float v0, float v1, u32& lo_out) {
    __half h0, l0, h1, l1;
    split_h16(v0, h0, l0); split_h16(v1, h1, l1);
    lo_out = (u32)__half_as_ushort(l0) | ((u32)__half_as_ushort(l1) << 16);
    return (u32)__half_as_ushort(h0) | ((u32)__half_as_ushort(h1) << 16);
}
__device__ __forceinline__ void split_bf(float v, __nv_bfloat16& h, __nv_bfloat16& l) {
    h = __float2bfloat16(v);
    l = __float2bfloat16(v - __bfloat162float(h));
}
// gate-paired row -> j (j = gate*1024 + cell)
__device__ __forceinline__ int rowj(int nT, int n) {
    int half = n >> 6, m = n & 63;
    return (half * 2 + (m & 1)) * 1024 + nT * 32 + (m >> 1);
}

// ---------------- merged prep: convs + bias + flag init, one launch ----------------
__global__ void conv_all(const float* __restrict__ Whh, const float* __restrict__ Wih,
                         const float* __restrict__ Wout, const float* __restrict__ enc,
                         const float* __restrict__ bih, const float* __restrict__ bhh,
                         const float* __restrict__ bout)
{
    int b = blockIdx.x;
    int tid = threadIdx.x, w = tid >> 5, lane = tid & 31;

    if (b < 512) {                      // conv_w0: Whh -> g_wbf[0]
        int chunk = b & 15, nT = b >> 4;
        char* th = (char*)&g_wbf[0][nT][chunk][0];
#pragma unroll
        for (int r = 0; r < 16; r++) {
            int n = r * 8 + w;
            const float2 v2 = *(const float2*)&Whh[(size_t)rowj(nT, n) * 1024 + chunk * 64 + lane * 2];
            u32 off = swz((u32)(n * 128 + lane * 4));
            *(u32*)(th + off) = pack2h(v2.x, v2.y);
        }
    } else if (b < 640) {               // conv_wih -> g_pA (bf16 split)
        int idx = b - 512, oc = idx & 3, nT = idx >> 2;
        char* th = (char*)&g_pA[nT][oc][0][0];
        char* tl = th + 16384;
#pragma unroll
        for (int r = 0; r < 16; r++) {
            int n = r * 8 + w;
            const float2 v2 = *(const float2*)&Wih[(size_t)rowj(nT, n) * 256 + oc * 64 + lane * 2];
            __nv_bfloat16 h0, l0, h1, l1;
            split_bf(v2.x, h0, l0); split_bf(v2.y, h1, l1);
            u32 hi = (u32)__bfloat16_as_ushort(h0) | ((u32)__bfloat16_as_ushort(h1) << 16);
            u32 lo = (u32)__bfloat16_as_ushort(l0) | ((u32)__bfloat16_as_ushort(l1) << 16);
            u32 off = swz((u32)(n * 128 + lane * 4));
            *(u32*)(th + off) = hi;
            *(u32*)(tl + off) = lo;
        }
    } else if (b < 704) {               // conv_woutT -> g_pB (bf16 split)
        int idx = b - 640, oc = idx & 3, kc = idx >> 2;
        int k = tid & 63, og = tid >> 6;
        char* th = (char*)&g_pB[kc][oc][0][0];
        char* tl = th + 8192;
#pragma unroll
        for (int i = 0; i < 16; i++) {
            int oo = og * 16 + i;
            float v = Wout[(size_t)(oc * 64 + oo) * 1024 + kc * 64 + k];
            __nv_bfloat16 h, l; split_bf(v, h, l);
            u32 off = swz((u32)(k * 128 + oo * 2));
            *(__nv_bfloat16*)(th + off) = h;
            *(__nv_bfloat16*)(tl + off) = l;
        }
    } else if (b < 736) {               // conv_obf -> g_obf (fp16 split; hi used)
        int idx = b - 704, chunk = idx & 15, nOT = idx >> 4;
        char* th = (char*)&g_obf[nOT][chunk][0][0];
        char* tl = th + 16384;
#pragma unroll
        for (int r = 0; r < 16; r++) {
            int n = r * 8 + w;
            const float2 v2 = *(const float2*)&Wout[(size_t)(nOT * 128 + n) * 1024 + chunk * 64 + lane * 2];
            u32 lo, hi = pack_split2h(v2.x, v2.y, lo);
            u32 off = swz((u32)(n * 128 + lane * 4));
            *(u32*)(th + off) = hi;
            *(u32*)(tl + off) = lo;
        }
    } else if (b < 800) {               // conv_h0 -> g_hbf[0]
        int idx = b - 736, chunk = idx & 15, mT = idx >> 4;
        char* th = (char*)&g_hbf[0][mT][chunk][0];
#pragma unroll
        for (int r = 0; r < 16; r++) {
            int m = r * 8 + w;
            const float2 v2 = *(const float2*)&enc[(size_t)(mT * 128 + m) * 1024 + chunk * 64 + lane * 2];
            u32 off = swz((u32)(m * 128 + lane * 4));
            *(u32*)(th + off) = pack2h(v2.x, v2.y);
        }
    } else if (b < 811) {               // flag init (g_bar 516 + g_bc 2064)
        int i = (b - 800) * 256 + tid;
        if (i < 516) g_bar[i] = 0;
        else if (i < 516 + 129 * 16) ((u32*)g_bc)[i - 516] = 0;
    } else {                            // prep_bias: blocks 811..1322, warp per j
        int j = (b - 811) * 8 + w;
        float acc = 0.f;
#pragma unroll
        for (int i = 0; i < 8; i++) acc += Wih[(size_t)j * 256 + i * 32 + lane] * bout[i * 32 + lane];
#pragma unroll
        for (int o = 16; o; o >>= 1) acc += __shfl_xor_sync(0xFFFFFFFFu, acc, o);
        if (lane == 0) {
            float s = bih[j] + bhh[j];
            g_b0[j] = s;
            g_bf[j] = s + acc;
        }
    }
}

// ---------------- prep GEMM: g_wbf[1] = fp16(Whh + Wih @ Wout^T), bf16 3-pass -------
#define PREP_SMEM (128*1024 + 64*1024 + 1024)
__global__ __launch_bounds__(256, 1) void prep_mma(const float* __restrict__ Whh)
{
    extern __shared__ char smem[];
    u32 sb = (smem_u32(smem) + 1023) & ~1023u;
    int tid = threadIdx.x, lane = tid & 31, w = tid >> 5;
    int nT = blockIdx.x, kc = blockIdx.y;

    const char* srcA = (const char*)&g_pA[nT][0][0][0];
    const char* srcB = (const char*)&g_pB[kc][0][0][0];
#pragma unroll
    for (int r = 0; r < 32; r++) { int idx = r * 256 + tid; cpa16(sb + idx * 16, srcA + (size_t)idx * 16); }
#pragma unroll
    for (int r = 0; r < 16; r++) { int idx = r * 256 + tid; cpa16(sb + 131072 + idx * 16, srcB + (size_t)idx * 16); }
    CP_COMMIT(); CP_WAIT0();
    __syncthreads();

    int wm = w >> 1, wn = w & 1;
    const int aRow = ((lane >> 3) & 1) * 8 + (lane & 7);
    const int aKh  = lane >> 4;
    const int bRow = (lane >> 4) * 8 + (lane & 7);
    const int bKh  = (lane >> 3) & 1;

    float d[2][4][4] = {};
#pragma unroll
    for (int oc = 0; oc < 4; oc++) {
        u32 stA = sb + oc * 32768;
        u32 stB = sb + 131072 + oc * 16384;
#pragma unroll
        for (int k16 = 0; k16 < 4; k16++) {
            u32 aH[2][4], aL[2][4];
#pragma unroll
            for (int mi = 0; mi < 2; mi++) {
                u32 off = swz((u32)((wm * 32 + mi * 16 + aRow) * 128 + (k16 * 2 + aKh) * 16));
                ldsm4(aH[mi], stA + off);
                ldsm4(aL[mi], stA + 16384 + off);
            }
            u32 bH[2][4], bL[2][4];
#pragma unroll
            for (int bi = 0; bi < 2; bi++) {
                u32 off = swz((u32)((wn * 32 + bi * 16 + bRow) * 128 + (k16 * 2 + bKh) * 16));
                ldsm4(bH[bi], stB + off);
                ldsm4(bL[bi], stB + 8192 + off);
            }
#pragma unroll
            for (int mi = 0; mi < 2; mi++)
#pragma unroll
                for (int nj = 0; nj < 4; nj++) {
                    mma_bf16(d[mi][nj], aH[mi], &bH[nj >> 1][(nj & 1) * 2]);
                    mma_bf16(d[mi][nj], aH[mi], &bL[nj >> 1][(nj & 1) * 2]);
                    mma_bf16(d[mi][nj], aL[mi], &bH[nj >> 1][(nj & 1) * 2]);
                }
        }
    }

    char* th = (char*)&g_wbf[1][nT][kc][0];
#pragma unroll
    for (int mi = 0; mi < 2; mi++)
#pragma unroll
        for (int nj = 0; nj < 4; nj++)
#pragma unroll
            for (int rh = 0; rh < 2; rh++) {
                int n = wm * 32 + mi * 16 + (lane >> 2) + rh * 8;
                int j = rowj(nT, n);
                int k0l = wn * 32 + nj * 8 + 2 * (lane & 3);
                const float* wr = Whh + (size_t)j * 1024 + kc * 64 + k0l;
                u32 off = swz((u32)(n * 128 + k0l * 2));
                *(u32*)(th + off) = pack2h(d[mi][nj][rh * 2 + 0] + wr[0],
                                           d[mi][nj][rh * 2 + 1] + wr[1]);
            }
}

// ---------------- unified persistent kernel: 128 LSTM CTAs + 20 output workers -------
#define BRES_BYTES 163840
#define LSTAGE 32768
#define OSTG 32768
#define LSTM_SMEM (1024 + 1024 + BRES_BYTES + 2*LSTAGE)
__global__ __launch_bounds__(256, 1) void persist(const float* __restrict__ bout,
                                                  float* __restrict__ out)
{
    extern __shared__ char smem[];
    u32 sb = (smem_u32(smem) + 1023) & ~1023u;
    const int tid = threadIdx.x, lane = tid & 31, w = tid >> 5;
    const int bid = blockIdx.x;
    const int wm = w >> 2, wn = w & 3;
    const int aRow = ((lane >> 3) & 1) * 8 + (lane & 7);
    const int aKh  = lane >> 4;
    const int bRow = (lane >> 4) * 8 + (lane & 7);
    const int bKh  = (lane >> 3) & 1;

    if (bid < 128) {
        // ================= LSTM role =================
        const int mT = bid >> 5, nT = bid & 31;
        const u32 mb0 = sb, mb1 = sb + 16, mbP = sb + 32;
        const u32 sbBres  = sb + 1024;
        const u32 sbStage = sbBres + BRES_BYTES;

        if (tid == 0) {
            mbar_init(mb0, 1);
            mbar_init(mb1, 1);
            mbar_init(mbP, 1);
            asm volatile("fence.proxy.async.shared::cta;" ::: "memory");
        }
        __syncthreads();

        if (tid == 0) {
            const char* wres = (const char*)&g_wbf[1][nT][0];
            mbar_expect(mbP, BRES_BYTES);
#pragma unroll
            for (int c = 0; c < 10; c++)
                bulk_g2s(sbBres + c * 16384, wres + (size_t)c * 16384, 16384, mbP);

            const char* B1 = (const char*)&g_wbf[0][nT][0];
            const char* A1 = (const char*)&g_hbf[0][mT][0];
            mbar_expect(mb0, 32768);
            bulk_g2s(sbStage, A1, 16384, mb0);
            bulk_g2s(sbStage + 16384, B1, 16384, mb0);
            mbar_expect(mb1, 32768);
            bulk_g2s(sbStage + LSTAGE, A1 + 16384, 16384, mb1);
            bulk_g2s(sbStage + LSTAGE + 16384, B1 + 16384, 16384, mb1);
        }
        mbar_wait(mbP, 0);

        float bZ[2][4], bF[2][4];
#pragma unroll
        for (int cp = 0; cp < 2; cp++) {
            int cell = nT * 32 + wn * 8 + cp * 4 + (lane & 3);
#pragma unroll
            for (int g = 0; g < 4; g++) {
                bZ[cp][g] = g_b0[g * 1024 + cell];
                bF[cp][g] = g_bf[g * 1024 + cell];
            }
        }

        float creg[4][2][2];
#pragma unroll
        for (int mi = 0; mi < 4; mi++)
#pragma unroll
            for (int rh = 0; rh < 2; rh++)
#pragma unroll
                for (int cp = 0; cp < 2; cp++) creg[mi][rh][cp] = 0.f;

        u32 ph0 = 0, ph1 = 0;

        for (int t = 1; t <= 128; t++) {
            const int first = (t == 1);
            const char* srcA = (const char*)&g_hbf[t - 1][mT][0];
            const char* srcB = first ? (const char*)&g_wbf[0][nT][0]
                                     : (const char*)&g_wbf[1][nT][0];

            float d[4][4][4];
#pragma unroll
            for (int mi = 0; mi < 4; mi++)
#pragma unroll
                for (int nj = 0; nj < 4; nj++)
#pragma unroll
                    for (int q = 0; q < 4; q++) d[mi][nj][q] = 0.f;

            for (int c = 0; c < 16; c++) {
                int s = c & 1;
                u32 mbs = s ? mb1 : mb0;
                if (s) { mbar_wait(mb1, ph1); ph1 ^= 1; }
                else   { mbar_wait(mb0, ph0); ph0 ^= 1; }
                u32 stA = sbStage + s * LSTAGE;
                u32 stB = (!first && c < 10) ? (sbBres + c * 16384) : (stA + 16384);
#pragma unroll
                for (int k16 = 0; k16 < 4; k16++) {
                    u32 aH[4][4];
#pragma unroll
                    for (int mi = 0; mi < 4; mi++) {
                        u32 off = swz((u32)((wm * 64 + mi * 16 + aRow) * 128 + (k16 * 2 + aKh) * 16));
                        ldsm4(aH[mi], stA + off);
                    }
                    u32 bIFh[4], bGOh[4];
                    {
                        u32 offIF = swz((u32)((wn * 16 + bRow) * 128 + (k16 * 2 + bKh) * 16));
                        u32 offGO = swz((u32)((64 + wn * 16 + bRow) * 128 + (k16 * 2 + bKh) * 16));
                        ldsm4(bIFh, stB + offIF);
                        ldsm4(bGOh, stB + offGO);
                    }
#pragma unroll
                    for (int mi = 0; mi < 4; mi++)
#pragma unroll
                        for (int nj = 0; nj < 2; nj++) {
                            mma_f16(d[mi][nj],     aH[mi], &bIFh[nj * 2]);
                            mma_f16(d[mi][nj + 2], aH[mi], &bGOh[nj * 2]);
                        }
                }
                __syncthreads();   // all warps done with stage s -> safe to refill
                if (tid == 0 && c + 2 < 16) {
                    int cn = c + 2;
                    if (!first) {
                        if (cn == 2)      { flag_wait(&g_bc[t - 1][mT][2], 2); FENCE_ACQ(); }
                        else if (cn == 3) { flag_wait(&g_bar[(t - 1) * 4 + mT], 32); FENCE_ACQ(); }
                        // cn >= 4: full barrier already observed at cn==3
                    }
                    int bStream = (first || cn >= 10);
                    mbar_expect(mbs, bStream ? 32768u : 16384u);
                    bulk_g2s(stA, srcA + (size_t)cn * 16384, 16384, mbs);
                    if (bStream)
                        bulk_g2s(stA + 16384, srcB + (size_t)cn * 16384, 16384, mbs);
                }
            }

            // ---- epilogue: cell update (c in regs, fast nonlinearities) ----
            {
                const int chunk = nT >> 1;
                char* dh = (char*)&g_hbf[t][mT][chunk][0];
#pragma unroll
                for (int mi = 0; mi < 4; mi++)
#pragma unroll
                    for (int rh = 0; rh < 2; rh++) {
                        int bl = wm * 64 + mi * 16 + (lane >> 2) + rh * 8;
#pragma unroll
                        for (int cp = 0; cp < 2; cp++) {
                            int cl = wn * 8 + cp * 4 + (lane & 3);
                            float gi = d[mi][cp][rh * 2 + 0]     + (first ? bZ[cp][0] : bF[cp][0]);
                            float gf = d[mi][cp][rh * 2 + 1]     + (first ? bZ[cp][1] : bF[cp][1]);
                            float gg = d[mi][cp + 2][rh * 2 + 0] + (first ? bZ[cp][2] : bF[cp][2]);
                            float go = d[mi][cp + 2][rh * 2 + 1] + (first ? bZ[cp][3] : bF[cp][3]);
                            float cold = first ? 0.f : creg[mi][rh][cp];
                            float cn = sigm(gf) * cold + sigm(gi) * ftanh(gg);
                            float hn = sigm(go) * ftanh(cn);
                            creg[mi][rh][cp] = cn;
                            int kin = (nT & 1) * 32 + cl;
                            u32 off = swz((u32)(bl * 128 + kin * 2));
                            *(__half*)(dh + off) = __float2half_rn(hn);
                        }
                    }
            }

            __syncthreads();                 // all epilogue STGs issued
            if (tid == 0) {
                if (nT < 6) rel_add(&g_bc[t][mT][nT >> 1]);   // chunk 0/1/2 ready counters
                rel_add(&g_bar[t * 4 + mT]);                   // full counter
                if (t < 128) {
                    const char* An = (const char*)&g_hbf[t][mT][0];
                    flag_wait(&g_bc[t][mT][0], 2);
                    FENCE_ACQ();
                    mbar_expect(mb0, 16384);
                    bulk_g2s(sbStage, An, 16384, mb0);
                    flag_wait(&g_bc[t][mT][1], 2);
                    FENCE_ACQ();
                    mbar_expect(mb1, 16384);
                    bulk_g2s(sbStage + LSTAGE, An + 16384, 16384, mb1);
                }
            }
            // no trailing __syncthreads: non-tid0 threads block on the phase-tracked mbarriers
        }
    } else {
        // ================= output worker role =================
        const int wk = bid - 128;   // 0..19
        const u32 mb0 = sb, mb1 = sb + 16;
        const u32 stg = sb + 1024;

        if (tid == 0) {
            mbar_init(mb0, 1);
            mbar_init(mb1, 1);
            asm volatile("fence.proxy.async.shared::cta;" ::: "memory");
        }
        __syncthreads();

        u32 ph0 = 0, ph1 = 0;

        for (int job = wk; job < 1024; job += 20) {
            const int t   = (job >> 3) + 1;       // h step 1..128
            const int mT  = job & 3;
            const int nOT = (job >> 2) & 1;

            if (tid == 0) {
                const u32* bp = &g_bar[t * 4 + mT];
                u32 v;
                asm volatile("ld.relaxed.gpu.global.u32 %0, [%1];" : "=r"(v) : "l"(bp) : "memory");
                while (v < 32) {
                    asm volatile("nanosleep.u32 64;");
                    asm volatile("ld.relaxed.gpu.global.u32 %0, [%1];" : "=r"(v) : "l"(bp) : "memory");
                }
                FENCE_ACQ();
            }
            __syncthreads();

            const char* srcA = (const char*)&g_hbf[t][mT][0];       // 16KB/chunk
            const char* srcB = (const char*)&g_obf[nOT][0][0][0];   // hi at +0, 32KB stride

            if (tid == 0) {
                mbar_expect(mb0, 32768);
                bulk_g2s(stg, srcA, 16384, mb0);
                bulk_g2s(stg + 16384, srcB, 16384, mb0);
                mbar_expect(mb1, 32768);
                bulk_g2s(stg + OSTG, srcA + 16384, 16384, mb1);
                bulk_g2s(stg + OSTG + 16384, srcB + 32768, 16384, mb1);
            }

            float d[4][4][4];
#pragma unroll
            for (int mi = 0; mi < 4; mi++)
#pragma unroll
                for (int nj = 0; nj < 4; nj++)
#pragma unroll
                    for (int q = 0; q < 4; q++) d[mi][nj][q] = 0.f;

            for (int c = 0; c < 16; c++) {
                int s = c & 1;
                u32 mbs = s ? mb1 : mb0;
                if (s) { mbar_wait(mb1, ph1); ph1 ^= 1; }
                else   { mbar_wait(mb0, ph0); ph0 ^= 1; }
                u32 stA = stg + s * OSTG;
                u32 stB = stA + 16384;
#pragma unroll
                for (int k16 = 0; k16 < 4; k16++) {
                    u32 aH[4][4];
#pragma unroll
                    for (int mi = 0; mi < 4; mi++) {
                        u32 off = swz((u32)((wm * 64 + mi * 16 + aRow) * 128 + (k16 * 2 + aKh) * 16));
                        ldsm4(aH[mi], stA + off);
                    }
                    u32 bH[2][4];
#pragma unroll
                    for (int bi = 0; bi < 2; bi++) {
                        u32 off = swz((u32)((wn * 32 + bi * 16 + bRow) * 128 + (k16 * 2 + bKh) * 16));
                        ldsm4(bH[bi], stB + off);
                    }
#pragma unroll
                    for (int mi = 0; mi < 4; mi++)
#pragma unroll
                        for (int nj = 0; nj < 4; nj++)
                            mma_f16(d[mi][nj], aH[mi], &bH[nj >> 1][(nj & 1) * 2]);
                }
                __syncthreads();
                if (tid == 0 && c + 2 < 16) {
                    int cn = c + 2;
                    mbar_expect(mbs, 32768);
                    bulk_g2s(stA, srcA + (size_t)cn * 16384, 16384, mbs);
                    bulk_g2s(stB, srcB + (size_t)cn * 32768, 16384, mbs);
                }
            }

#pragma unroll
            for (int mi = 0; mi < 4; mi++)
#pragma unroll
                for (int nj = 0; nj < 4; nj++)
#pragma unroll
                    for (int rh = 0; rh < 2; rh++) {
                        int bl = wm * 64 + mi * 16 + (lane >> 2) + rh * 8;
                        int b = mT * 128 + bl;
                        int o = nOT * 128 + wn * 32 + nj * 8 + 2 * (lane & 3);
                        float2 v = make_float2(d[mi][nj][rh * 2 + 0] + bout[o],
                                               d[mi][nj][rh * 2 + 1] + bout[o + 1]);
                        *(float2*)&out[(size_t)b * 32768 + (size_t)(t - 1) * 256 + o] = v;
                    }
        }
    }
}

// ---------------- launch ----------------
extern "C" void kernel_launch(void* const* d_in, const int* in_sizes, int n_in,
                              void* d_out, int out_size)
{
    const float *enc = nullptr, *Wih = nullptr, *Whh = nullptr;
    const float *bih = nullptr, *bhh = nullptr, *Wout = nullptr, *bout = nullptr;
    for (int i = 0; i < n_in; i++) {
        int s = in_sizes[i];
        if      (s == 512 * 1024)  enc  = (const float*)d_in[i];
        else if (s == 4096 * 256)  Wih  = (const float*)d_in[i];
        else if (s == 4096 * 1024) Whh  = (const float*)d_in[i];
        else if (s == 4096)        { if (!bih) bih = (const float*)d_in[i]; else bhh = (const float*)d_in[i]; }
        else if (s == 256 * 1024)  Wout = (const float*)d_in[i];
        else if (s == 256)         bout = (const float*)d_in[i];
    }
    if (!enc || !Wih || !Whh || !bih || !bhh || !Wout || !bout) return;

    cudaFuncSetAttribute(prep_mma, cudaFuncAttributeMaxDynamicSharedMemorySize, PREP_SMEM);
    cudaFuncSetAttribute(persist,  cudaFuncAttributeMaxDynamicSharedMemorySize, LSTM_SMEM);

    conv_all<<<1323, 256>>>(Whh, Wih, Wout, enc, bih, bhh, bout);
    prep_mma<<<dim3(32, 16), 256, PREP_SMEM>>>(Whh);
    persist<<<148, 256, LSTM_SMEM>>>(bout, (float*)d_out);
    (void)out_size;
}

// round 16
// speedup vs baseline: 1.2799x; 1.1249x over previous
#include <cuda_runtime.h>
#include <cuda_bf16.h>
#include <cuda_fp16.h>
#include <cstdint>

typedef unsigned long long ull;
typedef unsigned int u32;

// ---------------- scratch (static __device__, no allocations) ----------------
static __device__ float g_b0[4096];               // b_ih+b_hh
static __device__ float g_bf[4096];               // + W_ih@b_out
static __device__ u32   g_bar[516];               // per-(t,mT) full counters (target 32)
// fp16 HI-ONLY weight tiles, gate-paired rows, SW128: [src][nT 32][sub 16][128x64]
static __device__ __align__(256) __half g_wbf[2][32][16][8192];
// fp16 HI-ONLY hidden tiles: [t 0..128][mT 4][sub 16][128x64]
static __device__ __align__(256) __half g_hbf[129][4][16][8192];
// fp16 HI-ONLY output-weight tiles: [nOT 2][sub 16][128x64]
static __device__ __align__(256) __half g_obf[2][16][8192];
// prep-GEMM operands (bf16 split, 3-pass prep path)
static __device__ __align__(256) __nv_bfloat16 g_pA[32][4][2][8192];
static __device__ __align__(256) __nv_bfloat16 g_pB[16][4][2][4096];

// ---------------- helpers ----------------
__device__ __forceinline__ float sigm(float x)  { return __fdividef(1.0f, 1.0f + __expf(-x)); }
__device__ __forceinline__ float ftanh(float x) { return __fdividef(2.0f, 1.0f + __expf(-2.0f * x)) - 1.0f; }
__device__ __forceinline__ u32 swz(u32 x) { return x ^ ((x >> 3) & 0x70); }
__device__ __forceinline__ u32 smem_u32(const void* p) {
    u32 a; asm("{ .reg .u64 t; cvta.to.shared.u64 t, %1; cvt.u32.u64 %0, t; }" : "=r"(a) : "l"(p));
    return a;
}
__device__ __forceinline__ void cpa16(u32 dst, const void* src) {
    asm volatile("cp.async.cg.shared.global [%0], [%1], 16;" :: "r"(dst), "l"(src));
}
#define CP_COMMIT() asm volatile("cp.async.commit_group;" ::: "memory")
#define CP_WAIT0()  asm volatile("cp.async.wait_group 0;" ::: "memory")

// ---- bulk copy + mbarrier ----
__device__ __forceinline__ void bulk_g2s(u32 dst, const void* src, u32 bytes, u32 mbar) {
    asm volatile("cp.async.bulk.shared::cta.global.mbarrier::complete_tx::bytes [%0], [%1], %2, [%3];"
                 :: "r"(dst), "l"(src), "r"(bytes), "r"(mbar) : "memory");
}
__device__ __forceinline__ void mbar_init(u32 a, u32 cnt) {
    asm volatile("mbarrier.init.shared.b64 [%0], %1;" :: "r"(a), "r"(cnt) : "memory");
}
__device__ __forceinline__ void mbar_expect(u32 a, u32 tx) {
    asm volatile("mbarrier.arrive.expect_tx.shared.b64 _, [%0], %1;" :: "r"(a), "r"(tx) : "memory");
}
__device__ __forceinline__ void mbar_wait(u32 a, u32 ph) {
    asm volatile("{\n\t.reg .pred P;\n\t"
                 "WL_%=:\n\t"
                 "mbarrier.try_wait.parity.acquire.cta.shared::cta.b64 P, [%0], %1, 0x989680;\n\t"
                 "@P bra.uni WD_%=;\n\t"
                 "bra.uni WL_%=;\n\t"
                 "WD_%=:\n\t}"
                 :: "r"(a), "r"(ph) : "memory");
}
__device__ __forceinline__ void flag_wait(const u32* p, u32 tgt) {
    u32 v;
    asm volatile("ld.relaxed.gpu.global.u32 %0, [%1];" : "=r"(v) : "l"(p) : "memory");
    while (v < tgt) {
        asm volatile("nanosleep.u32 16;");
        asm volatile("ld.relaxed.gpu.global.u32 %0, [%1];" : "=r"(v) : "l"(p) : "memory");
    }
}
#define FENCE_ACQ() asm volatile("fence.acquire.gpu;" ::: "memory")
__device__ __forceinline__ void rel_add(u32* p) {
    asm volatile("red.release.gpu.global.add.u32 [%0], %1;" :: "l"(p), "r"(1u) : "memory");
}

__device__ __forceinline__ void ldsm4(u32* r, u32 addr) {
    asm volatile("ldmatrix.sync.aligned.m8n8.x4.shared.b16 {%0,%1,%2,%3}, [%4];"
                 : "=r"(r[0]), "=r"(r[1]), "=r"(r[2]), "=r"(r[3]) : "r"(addr));
}
__device__ __forceinline__ void mma_bf16(float* d, const u32* a, const u32* b) {
    asm volatile("mma.sync.aligned.m16n8k16.row.col.f32.bf16.bf16.f32 "
                 "{%0,%1,%2,%3}, {%4,%5,%6,%7}, {%8,%9}, {%0,%1,%2,%3};"
                 : "+f"(d[0]), "+f"(d[1]), "+f"(d[2]), "+f"(d[3])
                 : "r"(a[0]), "r"(a[1]), "r"(a[2]), "r"(a[3]), "r"(b[0]), "r"(b[1]));
}
__device__ __forceinline__ void mma_f16(float* d, const u32* a, const u32* b) {
    asm volatile("mma.sync.aligned.m16n8k16.row.col.f32.f16.f16.f32 "
                 "{%0,%1,%2,%3}, {%4,%5,%6,%7}, {%8,%9}, {%0,%1,%2,%3};"
                 : "+f"(d[0]), "+f"(d[1]), "+f"(d[2]), "+f"(d[3])
                 : "r"(a[0]), "r"(a[1]), "r"(a[2]), "r"(a[3]), "r"(b[0]), "r"(b[1]));
}
__device__ __forceinline__ void split_h16(float v, __half& h, __half& l) {
    h = __float2half_rn(v);
    l = __float2half_rn(v - __half2float(h));
}
__device__ __forceinline__ u32 pack2h(float v0, float v1) {
    __half h0 = __float2half_rn(v0), h1 = __float2half_rn(v1);
    return (u32)__half_as_ushort(h0) | ((u32)__half_as_ushort(h1) << 16);
}
__device__ __forceinline__ void split_bf(float v, __nv_bfloat16& h, __nv_bfloat16& l) {
    h = __float2bfloat16(v);
    l = __float2bfloat16(v - __bfloat162float(h));
}
// gate-paired row -> j (j = gate*1024 + cell)
__device__ __forceinline__ int rowj(int nT, int n) {
    int half = n >> 6, m = n & 63;
    return (half * 2 + (m & 1)) * 1024 + nT * 32 + (m >> 1);
}

// ---------------- merged prep: convs + bias + flag init, one launch ----------------
__global__ void conv_all(const float* __restrict__ Whh, const float* __restrict__ Wih,
                         const float* __restrict__ Wout, const float* __restrict__ enc,
                         const float* __restrict__ bih, const float* __restrict__ bhh,
                         const float* __restrict__ bout)
{
    int b = blockIdx.x;
    int tid = threadIdx.x, w = tid >> 5, lane = tid & 31;

    if (b < 512) {                      // conv_w0: Whh -> g_wbf[0]
        int chunk = b & 15, nT = b >> 4;
        char* th = (char*)&g_wbf[0][nT][chunk][0];
#pragma unroll
        for (int r = 0; r < 16; r++) {
            int n = r * 8 + w;
            const float2 v2 = *(const float2*)&Whh[(size_t)rowj(nT, n) * 1024 + chunk * 64 + lane * 2];
            u32 off = swz((u32)(n * 128 + lane * 4));
            *(u32*)(th + off) = pack2h(v2.x, v2.y);
        }
    } else if (b < 640) {               // conv_wih -> g_pA (bf16 split)
        int idx = b - 512, oc = idx & 3, nT = idx >> 2;
        char* th = (char*)&g_pA[nT][oc][0][0];
        char* tl = th + 16384;
#pragma unroll
        for (int r = 0; r < 16; r++) {
            int n = r * 8 + w;
            const float2 v2 = *(const float2*)&Wih[(size_t)rowj(nT, n) * 256 + oc * 64 + lane * 2];
            __nv_bfloat16 h0, l0, h1, l1;
            split_bf(v2.x, h0, l0); split_bf(v2.y, h1, l1);
            u32 hi = (u32)__bfloat16_as_ushort(h0) | ((u32)__bfloat16_as_ushort(h1) << 16);
            u32 lo = (u32)__bfloat16_as_ushort(l0) | ((u32)__bfloat16_as_ushort(l1) << 16);
            u32 off = swz((u32)(n * 128 + lane * 4));
            *(u32*)(th + off) = hi;
            *(u32*)(tl + off) = lo;
        }
    } else if (b < 704) {               // conv_woutT -> g_pB (bf16 split)
        int idx = b - 640, oc = idx & 3, kc = idx >> 2;
        int k = tid & 63, og = tid >> 6;
        char* th = (char*)&g_pB[kc][oc][0][0];
        char* tl = th + 8192;
#pragma unroll
        for (int i = 0; i < 16; i++) {
            int oo = og * 16 + i;
            float v = Wout[(size_t)(oc * 64 + oo) * 1024 + kc * 64 + k];
            __nv_bfloat16 h, l; split_bf(v, h, l);
            u32 off = swz((u32)(k * 128 + oo * 2));
            *(__nv_bfloat16*)(th + off) = h;
            *(__nv_bfloat16*)(tl + off) = l;
        }
    } else if (b < 736) {               // conv_obf -> g_obf (fp16 hi-only)
        int idx = b - 704, chunk = idx & 15, nOT = idx >> 4;
        char* th = (char*)&g_obf[nOT][chunk][0];
#pragma unroll
        for (int r = 0; r < 16; r++) {
            int n = r * 8 + w;
            const float2 v2 = *(const float2*)&Wout[(size_t)(nOT * 128 + n) * 1024 + chunk * 64 + lane * 2];
            u32 off = swz((u32)(n * 128 + lane * 4));
            *(u32*)(th + off) = pack2h(v2.x, v2.y);
        }
    } else if (b < 800) {               // conv_h0 -> g_hbf[0]
        int idx = b - 736, chunk = idx & 15, mT = idx >> 4;
        char* th = (char*)&g_hbf[0][mT][chunk][0];
#pragma unroll
        for (int r = 0; r < 16; r++) {
            int m = r * 8 + w;
            const float2 v2 = *(const float2*)&enc[(size_t)(mT * 128 + m) * 1024 + chunk * 64 + lane * 2];
            u32 off = swz((u32)(m * 128 + lane * 4));
            *(u32*)(th + off) = pack2h(v2.x, v2.y);
        }
    } else if (b < 804) {               // flag init
        int i = (b - 800) * 256 + tid;
        if (i < 516) g_bar[i] = 0;
    } else {                            // prep_bias: blocks 804..1315, warp per j
        int j = (b - 804) * 8 + w;
        float acc = 0.f;
#pragma unroll
        for (int i = 0; i < 8; i++) acc += Wih[(size_t)j * 256 + i * 32 + lane] * bout[i * 32 + lane];
#pragma unroll
        for (int o = 16; o; o >>= 1) acc += __shfl_xor_sync(0xFFFFFFFFu, acc, o);
        if (lane == 0) {
            float s = bih[j] + bhh[j];
            g_b0[j] = s;
            g_bf[j] = s + acc;
        }
    }
}

// ---------------- prep GEMM: g_wbf[1] = fp16(Whh + Wih @ Wout^T), bf16 3-pass -------
#define PREP_SMEM (128*1024 + 64*1024 + 1024)
__global__ __launch_bounds__(256, 1) void prep_mma(const float* __restrict__ Whh)
{
    extern __shared__ char smem[];
    u32 sb = (smem_u32(smem) + 1023) & ~1023u;
    int tid = threadIdx.x, lane = tid & 31, w = tid >> 5;
    int nT = blockIdx.x, kc = blockIdx.y;

    const char* srcA = (const char*)&g_pA[nT][0][0][0];
    const char* srcB = (const char*)&g_pB[kc][0][0][0];
#pragma unroll
    for (int r = 0; r < 32; r++) { int idx = r * 256 + tid; cpa16(sb + idx * 16, srcA + (size_t)idx * 16); }
#pragma unroll
    for (int r = 0; r < 16; r++) { int idx = r * 256 + tid; cpa16(sb + 131072 + idx * 16, srcB + (size_t)idx * 16); }
    CP_COMMIT(); CP_WAIT0();
    __syncthreads();

    int wm = w >> 1, wn = w & 1;
    const int aRow = ((lane >> 3) & 1) * 8 + (lane & 7);
    const int aKh  = lane >> 4;
    const int bRow = (lane >> 4) * 8 + (lane & 7);
    const int bKh  = (lane >> 3) & 1;

    float d[2][4][4] = {};
#pragma unroll
    for (int oc = 0; oc < 4; oc++) {
        u32 stA = sb + oc * 32768;
        u32 stB = sb + 131072 + oc * 16384;
#pragma unroll
        for (int k16 = 0; k16 < 4; k16++) {
            u32 aH[2][4], aL[2][4];
#pragma unroll
            for (int mi = 0; mi < 2; mi++) {
                u32 off = swz((u32)((wm * 32 + mi * 16 + aRow) * 128 + (k16 * 2 + aKh) * 16));
                ldsm4(aH[mi], stA + off);
                ldsm4(aL[mi], stA + 16384 + off);
            }
            u32 bH[2][4], bL[2][4];
#pragma unroll
            for (int bi = 0; bi < 2; bi++) {
                u32 off = swz((u32)((wn * 32 + bi * 16 + bRow) * 128 + (k16 * 2 + bKh) * 16));
                ldsm4(bH[bi], stB + off);
                ldsm4(bL[bi], stB + 8192 + off);
            }
#pragma unroll
            for (int mi = 0; mi < 2; mi++)
#pragma unroll
                for (int nj = 0; nj < 4; nj++) {
                    mma_bf16(d[mi][nj], aH[mi], &bH[nj >> 1][(nj & 1) * 2]);
                    mma_bf16(d[mi][nj], aH[mi], &bL[nj >> 1][(nj & 1) * 2]);
                    mma_bf16(d[mi][nj], aL[mi], &bH[nj >> 1][(nj & 1) * 2]);
                }
        }
    }

    char* th = (char*)&g_wbf[1][nT][kc][0];
#pragma unroll
    for (int mi = 0; mi < 2; mi++)
#pragma unroll
        for (int nj = 0; nj < 4; nj++)
#pragma unroll
            for (int rh = 0; rh < 2; rh++) {
                int n = wm * 32 + mi * 16 + (lane >> 2) + rh * 8;
                int j = rowj(nT, n);
                int k0l = wn * 32 + nj * 8 + 2 * (lane & 3);
                const float* wr = Whh + (size_t)j * 1024 + kc * 64 + k0l;
                u32 off = swz((u32)(n * 128 + k0l * 2));
                *(u32*)(th + off) = pack2h(d[mi][nj][rh * 2 + 0] + wr[0],
                                           d[mi][nj][rh * 2 + 1] + wr[1]);
            }
}

// ---------------- unified persistent kernel: 128 LSTM CTAs + 20 output workers -------
// LSTM smem: [mbars 1KB][3 stages x 64KB (A 32KB + B 32KB)]
#define LCHUNK 65536
#define LSTM_SMEM (1024 + 3*LCHUNK)
#define OSTG 65536
__global__ __launch_bounds__(256, 1) void persist(const float* __restrict__ bout,
                                                  float* __restrict__ out)
{
    extern __shared__ char smem[];
    u32 sb = (smem_u32(smem) + 1023) & ~1023u;
    const int tid = threadIdx.x, lane = tid & 31, w = tid >> 5;
    const int bid = blockIdx.x;
    const int wm = w >> 2, wn = w & 3;
    const int aRow = ((lane >> 3) & 1) * 8 + (lane & 7);
    const int aKh  = lane >> 4;
    const int bRow = (lane >> 4) * 8 + (lane & 7);
    const int bKh  = (lane >> 3) & 1;

    if (bid < 128) {
        // ================= LSTM role: 8 chunks/step, 3-stage, split A/B mbars =========
        const int mT = bid >> 5, nT = bid & 31;
        const u32 mbA = sb;          // +0,16,32
        const u32 mbB = sb + 48;     // +48,64,80
        const u32 sbStage = sb + 1024;

        if (tid == 0) {
#pragma unroll
            for (int i = 0; i < 3; i++) { mbar_init(mbA + 16 * i, 1); mbar_init(mbB + 16 * i, 1); }
            asm volatile("fence.proxy.async.shared::cta;" ::: "memory");
        }
        __syncthreads();

        const char* B0 = (const char*)&g_wbf[0][nT][0];   // Whh tiles (t=1)
        const char* Bn = (const char*)&g_wbf[1][nT][0];   // fused tiles (t>=2)

        if (tid == 0) {
            const char* A1 = (const char*)&g_hbf[0][mT][0];
#pragma unroll
            for (int i = 0; i < 3; i++) {
                u32 stA = sbStage + i * LCHUNK;
                mbar_expect(mbA + 16 * i, 32768);
                bulk_g2s(stA, A1 + (size_t)i * 32768, 32768, mbA + 16 * i);
                mbar_expect(mbB + 16 * i, 32768);
                bulk_g2s(stA + 32768, B0 + (size_t)i * 32768, 32768, mbB + 16 * i);
            }
        }

        float bZ[2][4], bF[2][4];
#pragma unroll
        for (int cp = 0; cp < 2; cp++) {
            int cell = nT * 32 + wn * 8 + cp * 4 + (lane & 3);
#pragma unroll
            for (int g = 0; g < 4; g++) {
                bZ[cp][g] = g_b0[g * 1024 + cell];
                bF[cp][g] = g_bf[g * 1024 + cell];
            }
        }

        float creg[4][2][2];
#pragma unroll
        for (int mi = 0; mi < 4; mi++)
#pragma unroll
            for (int rh = 0; rh < 2; rh++)
#pragma unroll
                for (int cp = 0; cp < 2; cp++) creg[mi][rh][cp] = 0.f;

        for (int t = 1; t <= 128; t++) {
            const int first = (t == 1);
            const char* srcA = (const char*)&g_hbf[t - 1][mT][0];   // 32KB chunks contiguous
            const int gbase = (t - 1) * 8;

            float d[4][4][4];
#pragma unroll
            for (int mi = 0; mi < 4; mi++)
#pragma unroll
                for (int nj = 0; nj < 4; nj++)
#pragma unroll
                    for (int q = 0; q < 4; q++) d[mi][nj][q] = 0.f;

            for (int c = 0; c < 8; c++) {
                const int g = gbase + c;
                const int sg = g % 3;
                const u32 ph = (u32)((g / 3) & 1);
                mbar_wait(mbA + 16 * sg, ph);
                mbar_wait(mbB + 16 * sg, ph);
                u32 stA0 = sbStage + sg * LCHUNK;
                u32 stB0 = stA0 + 32768;
#pragma unroll
                for (int half = 0; half < 2; half++) {
                    u32 stA = stA0 + half * 16384;
                    u32 stB = stB0 + half * 16384;
#pragma unroll
                    for (int k16 = 0; k16 < 4; k16++) {
                        u32 aH[4][4];
#pragma unroll
                        for (int mi = 0; mi < 4; mi++) {
                            u32 off = swz((u32)((wm * 64 + mi * 16 + aRow) * 128 + (k16 * 2 + aKh) * 16));
                            ldsm4(aH[mi], stA + off);
                        }
                        u32 bIFh[4], bGOh[4];
                        {
                            u32 offIF = swz((u32)((wn * 16 + bRow) * 128 + (k16 * 2 + bKh) * 16));
                            u32 offGO = swz((u32)((64 + wn * 16 + bRow) * 128 + (k16 * 2 + bKh) * 16));
                            ldsm4(bIFh, stB + offIF);
                            ldsm4(bGOh, stB + offGO);
                        }
#pragma unroll
                        for (int mi = 0; mi < 4; mi++)
#pragma unroll
                            for (int nj = 0; nj < 2; nj++) {
                                mma_f16(d[mi][nj],     aH[mi], &bIFh[nj * 2]);
                                mma_f16(d[mi][nj + 2], aH[mi], &bGOh[nj * 2]);
                            }
                    }
                }
                __syncthreads();   // stage sg fully drained -> safe to refill
                if (tid == 0) {
                    int gn = g + 3;
                    if (gn < 1024) {
                        int cn = gn & 7;
                        // B: h-independent, always issueable now (stage just drained)
                        const char* sB = (gn < 8) ? B0 : Bn;
                        mbar_expect(mbB + 16 * sg, 32768);
                        bulk_g2s(stB0, sB + (size_t)cn * 32768, 32768, mbB + 16 * sg);
                        // A: same-step chunks (cn>=3) only; cn<3 filled at boundary
                        if (cn >= 3) {
                            mbar_expect(mbA + 16 * sg, 32768);
                            bulk_g2s(stA0, srcA + (size_t)cn * 32768, 32768, mbA + 16 * sg);
                        }
                    }
                }
            }

            // ---- epilogue: cell update (c in regs, fast nonlinearities) ----
            {
                const int chunk = nT >> 1;   // 16KB sub-chunk index
                char* dh = (char*)&g_hbf[t][mT][chunk][0];
#pragma unroll
                for (int mi = 0; mi < 4; mi++)
#pragma unroll
                    for (int rh = 0; rh < 2; rh++) {
                        int bl = wm * 64 + mi * 16 + (lane >> 2) + rh * 8;
#pragma unroll
                        for (int cp = 0; cp < 2; cp++) {
                            int cl = wn * 8 + cp * 4 + (lane & 3);
                            float gi = d[mi][cp][rh * 2 + 0]     + (first ? bZ[cp][0] : bF[cp][0]);
                            float gf = d[mi][cp][rh * 2 + 1]     + (first ? bZ[cp][1] : bF[cp][1]);
                            float gg = d[mi][cp + 2][rh * 2 + 0] + (first ? bZ[cp][2] : bF[cp][2]);
                            float go = d[mi][cp + 2][rh * 2 + 1] + (first ? bZ[cp][3] : bF[cp][3]);
                            float cold = first ? 0.f : creg[mi][rh][cp];
                            float cn = sigm(gf) * cold + sigm(gi) * ftanh(gg);
                            float hn = sigm(go) * ftanh(cn);
                            creg[mi][rh][cp] = cn;
                            int kin = (nT & 1) * 32 + cl;
                            u32 off = swz((u32)(bl * 128 + kin * 2));
                            *(__half*)(dh + off) = __float2half_rn(hn);
                        }
                    }
            }

            __syncthreads();                 // all epilogue STGs issued
            if (tid == 0) {
                rel_add(&g_bar[t * 4 + mT]);
                if (t < 128) {
                    flag_wait(&g_bar[t * 4 + mT], 32);
                    FENCE_ACQ();
                    const char* An = (const char*)&g_hbf[t][mT][0];
#pragma unroll
                    for (int i = 0; i < 3; i++) {
                        int g0 = t * 8 + i;
                        int sg = g0 % 3;
                        mbar_expect(mbA + 16 * sg, 32768);
                        bulk_g2s(sbStage + sg * LCHUNK, An + (size_t)i * 32768, 32768, mbA + 16 * sg);
                    }
                }
            }
            // no trailing __syncthreads: non-tid0 threads block on the phase-tracked mbars
        }
    } else {
        // ================= output worker role: 8 chunks/job =================
        const int wk = bid - 128;   // 0..19
        const u32 mb0 = sb, mb1 = sb + 16;
        const u32 stg = sb + 1024;

        if (tid == 0) {
            mbar_init(mb0, 1);
            mbar_init(mb1, 1);
            asm volatile("fence.proxy.async.shared::cta;" ::: "memory");
        }
        __syncthreads();

        u32 ph0 = 0, ph1 = 0;

        for (int job = wk; job < 1024; job += 20) {
            const int t   = (job >> 3) + 1;       // h step 1..128
            const int mT  = job & 3;
            const int nOT = (job >> 2) & 1;

            if (tid == 0) {
                const u32* bp = &g_bar[t * 4 + mT];
                u32 v;
                asm volatile("ld.relaxed.gpu.global.u32 %0, [%1];" : "=r"(v) : "l"(bp) : "memory");
                while (v < 32) {
                    asm volatile("nanosleep.u32 64;");
                    asm volatile("ld.relaxed.gpu.global.u32 %0, [%1];" : "=r"(v) : "l"(bp) : "memory");
                }
                FENCE_ACQ();
            }
            __syncthreads();

            const char* srcA = (const char*)&g_hbf[t][mT][0];   // 32KB chunks contiguous
            const char* srcB = (const char*)&g_obf[nOT][0][0];  // hi-only, 32KB chunks contiguous

            if (tid == 0) {
#pragma unroll
                for (int pc = 0; pc < 2; pc++) {
                    u32 mbs = pc ? mb1 : mb0;
                    u32 st = stg + pc * OSTG;
                    mbar_expect(mbs, 65536);
                    bulk_g2s(st, srcA + (size_t)pc * 32768, 32768, mbs);
                    bulk_g2s(st + 32768, srcB + (size_t)pc * 32768, 32768, mbs);
                }
            }

            float d[4][4][4];
#pragma unroll
            for (int mi = 0; mi < 4; mi++)
#pragma unroll
                for (int nj = 0; nj < 4; nj++)
#pragma unroll
                    for (int q = 0; q < 4; q++) d[mi][nj][q] = 0.f;

            for (int c = 0; c < 8; c++) {
                int s = c & 1;
                u32 mbs = s ? mb1 : mb0;
                if (s) { mbar_wait(mb1, ph1); ph1 ^= 1; }
                else   { mbar_wait(mb0, ph0); ph0 ^= 1; }
                u32 stA0 = stg + s * OSTG;
                u32 stB0 = stA0 + 32768;
#pragma unroll
                for (int half = 0; half < 2; half++) {
                    u32 stA = stA0 + half * 16384;
                    u32 stB = stB0 + half * 16384;
#pragma unroll
                    for (int k16 = 0; k16 < 4; k16++) {
                        u32 aH[4][4];
#pragma unroll
                        for (int mi = 0; mi < 4; mi++) {
                            u32 off = swz((u32)((wm * 64 + mi * 16 + aRow) * 128 + (k16 * 2 + aKh) * 16));
                            ldsm4(aH[mi], stA + off);
                        }
                        u32 bH[2][4];
#pragma unroll
                        for (int bi = 0; bi < 2; bi++) {
                            u32 off = swz((u32)((wn * 32 + bi * 16 + bRow) * 128 + (k16 * 2 + bKh) * 16));
                            ldsm4(bH[bi], stB + off);
                        }
#pragma unroll
                        for (int mi = 0; mi < 4; mi++)
#pragma unroll
                            for (int nj = 0; nj < 4; nj++)
                                mma_f16(d[mi][nj], aH[mi], &bH[nj >> 1][(nj & 1) * 2]);
                    }
                }
                __syncthreads();
                if (tid == 0 && c + 2 < 8) {
                    int cn = c + 2;
                    mbar_expect(mbs, 65536);
                    bulk_g2s(stA0, srcA + (size_t)cn * 32768, 32768, mbs);
                    bulk_g2s(stB0, srcB + (size_t)cn * 32768, 32768, mbs);
                }
            }

#pragma unroll
            for (int mi = 0; mi < 4; mi++)
#pragma unroll
                for (int nj = 0; nj < 4; nj++)
#pragma unroll
                    for (int rh = 0; rh < 2; rh++) {
                        int bl = wm * 64 + mi * 16 + (lane >> 2) + rh * 8;
                        int b = mT * 128 + bl;
                        int o = nOT * 128 + wn * 32 + nj * 8 + 2 * (lane & 3);
                        float2 v = make_float2(d[mi][nj][rh * 2 + 0] + bout[o],
                                               d[mi][nj][rh * 2 + 1] + bout[o + 1]);
                        *(float2*)&out[(size_t)b * 32768 + (size_t)(t - 1) * 256 + o] = v;
                    }
        }
    }
}

// ---------------- launch ----------------
extern "C" void kernel_launch(void* const* d_in, const int* in_sizes, int n_in,
                              void* d_out, int out_size)
{
    const float *enc = nullptr, *Wih = nullptr, *Whh = nullptr;
    const float *bih = nullptr, *bhh = nullptr, *Wout = nullptr, *bout = nullptr;
    for (int i = 0; i < n_in; i++) {
        int s = in_sizes[i];
        if      (s == 512 * 1024)  enc  = (const float*)d_in[i];
        else if (s == 4096 * 256)  Wih  = (const float*)d_in[i];
        else if (s == 4096 * 1024) Whh  = (const float*)d_in[i];
        else if (s == 4096)        { if (!bih) bih = (const float*)d_in[i]; else bhh = (const float*)d_in[i]; }
        else if (s == 256 * 1024)  Wout = (const float*)d_in[i];
        else if (s == 256)         bout = (const float*)d_in[i];
    }
    if (!enc || !Wih || !Whh || !bih || !bhh || !Wout || !bout) return;

    cudaFuncSetAttribute(prep_mma, cudaFuncAttributeMaxDynamicSharedMemorySize, PREP_SMEM);
    cudaFuncSetAttribute(persist,  cudaFuncAttributeMaxDynamicSharedMemorySize, LSTM_SMEM);

    conv_all<<<1316, 256>>>(Whh, Wih, Wout, enc, bih, bhh, bout);
    prep_mma<<<dim3(32, 16), 256, PREP_SMEM>>>(Whh);
    persist<<<148, 256, LSTM_SMEM>>>(bout, (float*)d_out);
    (void)out_size;
}

// round 17
// speedup vs baseline: 1.2882x; 1.0064x over previous
#include <cuda_runtime.h>
#include <cuda_bf16.h>
#include <cuda_fp16.h>
#include <cstdint>

typedef unsigned long long ull;
typedef unsigned int u32;

// ---------------- scratch (static __device__, no allocations) ----------------
static __device__ float g_b0[4096];               // b_ih+b_hh
static __device__ float g_bf[4096];               // + W_ih@b_out
static __device__ u32   g_bar[516];               // per-(t,mT) full counters (target 32)
static __device__ u32   g_prep;                   // prep-job completion counter (target 512)
// fp16 HI-ONLY weight tiles, gate-paired rows, SW128: [src][nT 32][sub 16][128x64]
static __device__ __align__(256) __half g_wbf[2][32][16][8192];
// fp16 HI-ONLY hidden tiles: [t 0..128][mT 4][sub 16][128x64]
static __device__ __align__(256) __half g_hbf[129][4][16][8192];
// fp16 HI-ONLY output-weight tiles: [nOT 2][sub 16][128x64]
static __device__ __align__(256) __half g_obf[2][16][8192];
// prep-GEMM operands (bf16 split, 3-pass prep path)
static __device__ __align__(256) __nv_bfloat16 g_pA[32][4][2][8192];
static __device__ __align__(256) __nv_bfloat16 g_pB[16][4][2][4096];

// ---------------- helpers ----------------
__device__ __forceinline__ float sigm(float x)  { return __fdividef(1.0f, 1.0f + __expf(-x)); }
__device__ __forceinline__ float ftanh(float x) { return __fdividef(2.0f, 1.0f + __expf(-2.0f * x)) - 1.0f; }
__device__ __forceinline__ u32 swz(u32 x) { return x ^ ((x >> 3) & 0x70); }
__device__ __forceinline__ u32 smem_u32(const void* p) {
    u32 a; asm("{ .reg .u64 t; cvta.to.shared.u64 t, %1; cvt.u32.u64 %0, t; }" : "=r"(a) : "l"(p));
    return a;
}
__device__ __forceinline__ void cpa16(u32 dst, const void* src) {
    asm volatile("cp.async.cg.shared.global [%0], [%1], 16;" :: "r"(dst), "l"(src));
}
#define CP_COMMIT() asm volatile("cp.async.commit_group;" ::: "memory")
#define CP_WAIT0()  asm volatile("cp.async.wait_group 0;" ::: "memory")

// ---- bulk copy + mbarrier ----
__device__ __forceinline__ void bulk_g2s(u32 dst, const void* src, u32 bytes, u32 mbar) {
    asm volatile("cp.async.bulk.shared::cta.global.mbarrier::complete_tx::bytes [%0], [%1], %2, [%3];"
                 :: "r"(dst), "l"(src), "r"(bytes), "r"(mbar) : "memory");
}
__device__ __forceinline__ void mbar_init(u32 a, u32 cnt) {
    asm volatile("mbarrier.init.shared.b64 [%0], %1;" :: "r"(a), "r"(cnt) : "memory");
}
__device__ __forceinline__ void mbar_expect(u32 a, u32 tx) {
    asm volatile("mbarrier.arrive.expect_tx.shared.b64 _, [%0], %1;" :: "r"(a), "r"(tx) : "memory");
}
__device__ __forceinline__ void mbar_wait(u32 a, u32 ph) {
    asm volatile("{\n\t.reg .pred P;\n\t"
                 "WL_%=:\n\t"
                 "mbarrier.try_wait.parity.acquire.cta.shared::cta.b64 P, [%0], %1, 0x989680;\n\t"
                 "@P bra.uni WD_%=;\n\t"
                 "bra.uni WL_%=;\n\t"
                 "WD_%=:\n\t}"
                 :: "r"(a), "r"(ph) : "memory");
}
__device__ __forceinline__ void flag_wait(const u32* p, u32 tgt) {
    u32 v;
    asm volatile("ld.relaxed.gpu.global.u32 %0, [%1];" : "=r"(v) : "l"(p) : "memory");
    while (v < tgt) {
        asm volatile("nanosleep.u32 16;");
        asm volatile("ld.relaxed.gpu.global.u32 %0, [%1];" : "=r"(v) : "l"(p) : "memory");
    }
}
#define FENCE_ACQ() asm volatile("fence.acquire.gpu;" ::: "memory")
__device__ __forceinline__ void rel_add(u32* p) {
    asm volatile("red.release.gpu.global.add.u32 [%0], %1;" :: "l"(p), "r"(1u) : "memory");
}

__device__ __forceinline__ void ldsm4(u32* r, u32 addr) {
    asm volatile("ldmatrix.sync.aligned.m8n8.x4.shared.b16 {%0,%1,%2,%3}, [%4];"
                 : "=r"(r[0]), "=r"(r[1]), "=r"(r[2]), "=r"(r[3]) : "r"(addr));
}
__device__ __forceinline__ void mma_bf16(float* d, const u32* a, const u32* b) {
    asm volatile("mma.sync.aligned.m16n8k16.row.col.f32.bf16.bf16.f32 "
                 "{%0,%1,%2,%3}, {%4,%5,%6,%7}, {%8,%9}, {%0,%1,%2,%3};"
                 : "+f"(d[0]), "+f"(d[1]), "+f"(d[2]), "+f"(d[3])
                 : "r"(a[0]), "r"(a[1]), "r"(a[2]), "r"(a[3]), "r"(b[0]), "r"(b[1]));
}
__device__ __forceinline__ void mma_f16(float* d, const u32* a, const u32* b) {
    asm volatile("mma.sync.aligned.m16n8k16.row.col.f32.f16.f16.f32 "
                 "{%0,%1,%2,%3}, {%4,%5,%6,%7}, {%8,%9}, {%0,%1,%2,%3};"
                 : "+f"(d[0]), "+f"(d[1]), "+f"(d[2]), "+f"(d[3])
                 : "r"(a[0]), "r"(a[1]), "r"(a[2]), "r"(a[3]), "r"(b[0]), "r"(b[1]));
}
__device__ __forceinline__ void split_h16(float v, __half& h, __half& l) {
    h = __float2half_rn(v);
    l = __float2half_rn(v - __half2float(h));
}
__device__ __forceinline__ u32 pack2h(float v0, float v1) {
    __half h0 = __float2half_rn(v0), h1 = __float2half_rn(v1);
    return (u32)__half_as_ushort(h0) | ((u32)__half_as_ushort(h1) << 16);
}
__device__ __forceinline__ void split_bf(float v, __nv_bfloat16& h, __nv_bfloat16& l) {
    h = __float2bfloat16(v);
    l = __float2bfloat16(v - __bfloat162float(h));
}
// gate-paired row -> j (j = gate*1024 + cell)
__device__ __forceinline__ int rowj(int nT, int n) {
    int half = n >> 6, m = n & 63;
    return (half * 2 + (m & 1)) * 1024 + nT * 32 + (m >> 1);
}

// ---------------- merged prep: convs + bias + flag init, one launch ----------------
__global__ void conv_all(const float* __restrict__ Whh, const float* __restrict__ Wih,
                         const float* __restrict__ Wout, const float* __restrict__ enc,
                         const float* __restrict__ bih, const float* __restrict__ bhh,
                         const float* __restrict__ bout)
{
    int b = blockIdx.x;
    int tid = threadIdx.x, w = tid >> 5, lane = tid & 31;

    if (b < 512) {                      // conv_w0: Whh -> g_wbf[0]
        int chunk = b & 15, nT = b >> 4;
        char* th = (char*)&g_wbf[0][nT][chunk][0];
#pragma unroll
        for (int r = 0; r < 16; r++) {
            int n = r * 8 + w;
            const float2 v2 = *(const float2*)&Whh[(size_t)rowj(nT, n) * 1024 + chunk * 64 + lane * 2];
            u32 off = swz((u32)(n * 128 + lane * 4));
            *(u32*)(th + off) = pack2h(v2.x, v2.y);
        }
    } else if (b < 640) {               // conv_wih -> g_pA (bf16 split)
        int idx = b - 512, oc = idx & 3, nT = idx >> 2;
        char* th = (char*)&g_pA[nT][oc][0][0];
        char* tl = th + 16384;
#pragma unroll
        for (int r = 0; r < 16; r++) {
            int n = r * 8 + w;
            const float2 v2 = *(const float2*)&Wih[(size_t)rowj(nT, n) * 256 + oc * 64 + lane * 2];
            __nv_bfloat16 h0, l0, h1, l1;
            split_bf(v2.x, h0, l0); split_bf(v2.y, h1, l1);
            u32 hi = (u32)__bfloat16_as_ushort(h0) | ((u32)__bfloat16_as_ushort(h1) << 16);
            u32 lo = (u32)__bfloat16_as_ushort(l0) | ((u32)__bfloat16_as_ushort(l1) << 16);
            u32 off = swz((u32)(n * 128 + lane * 4));
            *(u32*)(th + off) = hi;
            *(u32*)(tl + off) = lo;
        }
    } else if (b < 704) {               // conv_woutT -> g_pB (bf16 split)
        int idx = b - 640, oc = idx & 3, kc = idx >> 2;
        int k = tid & 63, og = tid >> 6;
        char* th = (char*)&g_pB[kc][oc][0][0];
        char* tl = th + 8192;
#pragma unroll
        for (int i = 0; i < 16; i++) {
            int oo = og * 16 + i;
            float v = Wout[(size_t)(oc * 64 + oo) * 1024 + kc * 64 + k];
            __nv_bfloat16 h, l; split_bf(v, h, l);
            u32 off = swz((u32)(k * 128 + oo * 2));
            *(__nv_bfloat16*)(th + off) = h;
            *(__nv_bfloat16*)(tl + off) = l;
        }
    } else if (b < 736) {               // conv_obf -> g_obf (fp16 hi-only)
        int idx = b - 704, chunk = idx & 15, nOT = idx >> 4;
        char* th = (char*)&g_obf[nOT][chunk][0];
#pragma unroll
        for (int r = 0; r < 16; r++) {
            int n = r * 8 + w;
            const float2 v2 = *(const float2*)&Wout[(size_t)(nOT * 128 + n) * 1024 + chunk * 64 + lane * 2];
            u32 off = swz((u32)(n * 128 + lane * 4));
            *(u32*)(th + off) = pack2h(v2.x, v2.y);
        }
    } else if (b < 800) {               // conv_h0 -> g_hbf[0]
        int idx = b - 736, chunk = idx & 15, mT = idx >> 4;
        char* th = (char*)&g_hbf[0][mT][chunk][0];
#pragma unroll
        for (int r = 0; r < 16; r++) {
            int m = r * 8 + w;
            const float2 v2 = *(const float2*)&enc[(size_t)(mT * 128 + m) * 1024 + chunk * 64 + lane * 2];
            u32 off = swz((u32)(m * 128 + lane * 4));
            *(u32*)(th + off) = pack2h(v2.x, v2.y);
        }
    } else if (b < 804) {               // flag init
        int i = (b - 800) * 256 + tid;
        if (i < 516) g_bar[i] = 0;
        if (i == 516) g_prep = 0;
    } else {                            // prep_bias: blocks 804..1315, warp per j
        int j = (b - 804) * 8 + w;
        float acc = 0.f;
#pragma unroll
        for (int i = 0; i < 8; i++) acc += Wih[(size_t)j * 256 + i * 32 + lane] * bout[i * 32 + lane];
#pragma unroll
        for (int o = 16; o; o >>= 1) acc += __shfl_xor_sync(0xFFFFFFFFu, acc, o);
        if (lane == 0) {
            float s = bih[j] + bhh[j];
            g_b0[j] = s;
            g_bf[j] = s + acc;
        }
    }
}

// ---------------- unified persistent kernel ----------------
// phase 0 (all CTAs): prep GEMM jobs -> g_wbf[1]; phase 1: 128 LSTM CTAs + 20 workers
#define LCHUNK 65536
#define LSTM_SMEM (1024 + 3*LCHUNK)
#define OSTG 65536
__global__ __launch_bounds__(256, 1) void persist(const float* __restrict__ Whh,
                                                  const float* __restrict__ bout,
                                                  float* __restrict__ out)
{
    extern __shared__ char smem[];
    u32 sb = (smem_u32(smem) + 1023) & ~1023u;
    const int tid = threadIdx.x, lane = tid & 31, w = tid >> 5;
    const int bid = blockIdx.x;
    const int wm = w >> 2, wn = w & 3;
    const int aRow = ((lane >> 3) & 1) * 8 + (lane & 7);
    const int aKh  = lane >> 4;
    const int bRow = (lane >> 4) * 8 + (lane & 7);
    const int bKh  = (lane >> 3) & 1;

    // ============ phase 0: prep GEMM jobs (all 148 CTAs, 148-stride over 512) ========
    {
        const u32 pb = sb + 1024;   // 192KB scratch: A 128KB @ +0, B 64KB @ +131072
        for (int job = bid; job < 512; job += 148) {
            int nT = job >> 4, kc = job & 15;
            const char* srcA = (const char*)&g_pA[nT][0][0][0];
            const char* srcB = (const char*)&g_pB[kc][0][0][0];
#pragma unroll
            for (int r = 0; r < 32; r++) { int idx = r * 256 + tid; cpa16(pb + idx * 16, srcA + (size_t)idx * 16); }
#pragma unroll
            for (int r = 0; r < 16; r++) { int idx = r * 256 + tid; cpa16(pb + 131072 + idx * 16, srcB + (size_t)idx * 16); }
            CP_COMMIT(); CP_WAIT0();
            __syncthreads();

            int pwm = w >> 1, pwn = w & 1;
            float d[2][4][4] = {};
#pragma unroll
            for (int oc = 0; oc < 4; oc++) {
                u32 stA = pb + oc * 32768;
                u32 stB = pb + 131072 + oc * 16384;
#pragma unroll
                for (int k16 = 0; k16 < 4; k16++) {
                    u32 aH[2][4], aL[2][4];
#pragma unroll
                    for (int mi = 0; mi < 2; mi++) {
                        u32 off = swz((u32)((pwm * 32 + mi * 16 + aRow) * 128 + (k16 * 2 + aKh) * 16));
                        ldsm4(aH[mi], stA + off);
                        ldsm4(aL[mi], stA + 16384 + off);
                    }
                    u32 bH[2][4], bL[2][4];
#pragma unroll
                    for (int bi = 0; bi < 2; bi++) {
                        u32 off = swz((u32)((pwn * 32 + bi * 16 + bRow) * 128 + (k16 * 2 + bKh) * 16));
                        ldsm4(bH[bi], stB + off);
                        ldsm4(bL[bi], stB + 8192 + off);
                    }
#pragma unroll
                    for (int mi = 0; mi < 2; mi++)
#pragma unroll
                        for (int nj = 0; nj < 4; nj++) {
                            mma_bf16(d[mi][nj], aH[mi], &bH[nj >> 1][(nj & 1) * 2]);
                            mma_bf16(d[mi][nj], aH[mi], &bL[nj >> 1][(nj & 1) * 2]);
                            mma_bf16(d[mi][nj], aL[mi], &bH[nj >> 1][(nj & 1) * 2]);
                        }
                }
            }

            char* th = (char*)&g_wbf[1][nT][kc][0];
#pragma unroll
            for (int mi = 0; mi < 2; mi++)
#pragma unroll
                for (int nj = 0; nj < 4; nj++)
#pragma unroll
                    for (int rh = 0; rh < 2; rh++) {
                        int n = pwm * 32 + mi * 16 + (lane >> 2) + rh * 8;
                        int j = rowj(nT, n);
                        int k0l = pwn * 32 + nj * 8 + 2 * (lane & 3);
                        const float* wr = Whh + (size_t)j * 1024 + kc * 64 + k0l;
                        u32 off = swz((u32)(n * 128 + k0l * 2));
                        *(u32*)(th + off) = pack2h(d[mi][nj][rh * 2 + 0] + wr[0],
                                                   d[mi][nj][rh * 2 + 1] + wr[1]);
                    }
            __syncthreads();                 // all stores done + scratch reusable
            if (tid == 0) rel_add(&g_prep);
        }
    }

    // ============ phase 1 ============
    if (bid < 128) {
        // ================= LSTM role: 8 chunks/step, 3-stage, merged count-2 mbars ====
        const int mT = bid >> 5, nT = bid & 31;
        const u32 mbS = sb;          // 3 mbars at +0,16,32, arrive count 2
        const u32 sbStage = sb + 1024;

        if (tid == 0) {
#pragma unroll
            for (int i = 0; i < 3; i++) mbar_init(mbS + 16 * i, 2);
            asm volatile("fence.proxy.async.shared::cta;" ::: "memory");
        }
        __syncthreads();

        const char* B0 = (const char*)&g_wbf[0][nT][0];   // Whh tiles (t=1)
        const char* Bn = (const char*)&g_wbf[1][nT][0];   // fused tiles (t>=2)

        if (tid == 0) {
            const char* A1 = (const char*)&g_hbf[0][mT][0];
#pragma unroll
            for (int i = 0; i < 3; i++) {
                u32 stA = sbStage + i * LCHUNK;
                mbar_expect(mbS + 16 * i, 32768);
                bulk_g2s(stA, A1 + (size_t)i * 32768, 32768, mbS + 16 * i);
                mbar_expect(mbS + 16 * i, 32768);
                bulk_g2s(stA + 32768, B0 + (size_t)i * 32768, 32768, mbS + 16 * i);
            }
        }

        float bZ[2][4], bF[2][4];
#pragma unroll
        for (int cp = 0; cp < 2; cp++) {
            int cell = nT * 32 + wn * 8 + cp * 4 + (lane & 3);
#pragma unroll
            for (int g = 0; g < 4; g++) {
                bZ[cp][g] = g_b0[g * 1024 + cell];
                bF[cp][g] = g_bf[g * 1024 + cell];
            }
        }

        float creg[4][2][2];
#pragma unroll
        for (int mi = 0; mi < 4; mi++)
#pragma unroll
            for (int rh = 0; rh < 2; rh++)
#pragma unroll
                for (int cp = 0; cp < 2; cp++) creg[mi][rh][cp] = 0.f;

        for (int t = 1; t <= 128; t++) {
            const int first = (t == 1);
            const char* srcA = (const char*)&g_hbf[t - 1][mT][0];
            const int gbase = (t - 1) * 8;

            float d[4][4][4];
#pragma unroll
            for (int mi = 0; mi < 4; mi++)
#pragma unroll
                for (int nj = 0; nj < 4; nj++)
#pragma unroll
                    for (int q = 0; q < 4; q++) d[mi][nj][q] = 0.f;

            for (int c = 0; c < 8; c++) {
                const int g = gbase + c;
                const int sg = g % 3;
                mbar_wait(mbS + 16 * sg, (u32)((g / 3) & 1));
                u32 stA0 = sbStage + sg * LCHUNK;
                u32 stB0 = stA0 + 32768;
#pragma unroll
                for (int half = 0; half < 2; half++) {
                    u32 stA = stA0 + half * 16384;
                    u32 stB = stB0 + half * 16384;
#pragma unroll
                    for (int k16 = 0; k16 < 4; k16++) {
                        u32 aH[4][4];
#pragma unroll
                        for (int mi = 0; mi < 4; mi++) {
                            u32 off = swz((u32)((wm * 64 + mi * 16 + aRow) * 128 + (k16 * 2 + aKh) * 16));
                            ldsm4(aH[mi], stA + off);
                        }
                        u32 bIFh[4], bGOh[4];
                        {
                            u32 offIF = swz((u32)((wn * 16 + bRow) * 128 + (k16 * 2 + bKh) * 16));
                            u32 offGO = swz((u32)((64 + wn * 16 + bRow) * 128 + (k16 * 2 + bKh) * 16));
                            ldsm4(bIFh, stB + offIF);
                            ldsm4(bGOh, stB + offGO);
                        }
#pragma unroll
                        for (int mi = 0; mi < 4; mi++)
#pragma unroll
                            for (int nj = 0; nj < 2; nj++) {
                                mma_f16(d[mi][nj],     aH[mi], &bIFh[nj * 2]);
                                mma_f16(d[mi][nj + 2], aH[mi], &bGOh[nj * 2]);
                            }
                    }
                }
                __syncthreads();   // stage sg fully drained -> safe to refill
                if (tid == 0) {
                    int gn = g + 3;
                    if (gn < 1024) {
                        int cn = gn & 7;
                        if (gn == 8) { flag_wait(&g_prep, 512); FENCE_ACQ(); }   // once
                        const char* sB = (gn < 8) ? B0 : Bn;
                        mbar_expect(mbS + 16 * sg, 32768);
                        bulk_g2s(stB0, sB + (size_t)cn * 32768, 32768, mbS + 16 * sg);
                        if (cn >= 3) {
                            mbar_expect(mbS + 16 * sg, 32768);
                            bulk_g2s(stA0, srcA + (size_t)cn * 32768, 32768, mbS + 16 * sg);
                        }
                    }
                }
            }

            // ---- epilogue: cell update (c in regs, fast nonlinearities) ----
            {
                const int chunk = nT >> 1;   // 16KB sub-chunk index
                char* dh = (char*)&g_hbf[t][mT][chunk][0];
#pragma unroll
                for (int mi = 0; mi < 4; mi++)
#pragma unroll
                    for (int rh = 0; rh < 2; rh++) {
                        int bl = wm * 64 + mi * 16 + (lane >> 2) + rh * 8;
#pragma unroll
                        for (int cp = 0; cp < 2; cp++) {
                            int cl = wn * 8 + cp * 4 + (lane & 3);
                            float gi = d[mi][cp][rh * 2 + 0]     + (first ? bZ[cp][0] : bF[cp][0]);
                            float gf = d[mi][cp][rh * 2 + 1]     + (first ? bZ[cp][1] : bF[cp][1]);
                            float gg = d[mi][cp + 2][rh * 2 + 0] + (first ? bZ[cp][2] : bF[cp][2]);
                            float go = d[mi][cp + 2][rh * 2 + 1] + (first ? bZ[cp][3] : bF[cp][3]);
                            float cold = first ? 0.f : creg[mi][rh][cp];
                            float cn = sigm(gf) * cold + sigm(gi) * ftanh(gg);
                            float hn = sigm(go) * ftanh(cn);
                            creg[mi][rh][cp] = cn;
                            int kin = (nT & 1) * 32 + cl;
                            u32 off = swz((u32)(bl * 128 + kin * 2));
                            *(__half*)(dh + off) = __float2half_rn(hn);
                        }
                    }
            }

            __syncthreads();                 // all epilogue STGs issued
            if (tid == 0) {
                rel_add(&g_bar[t * 4 + mT]);
                if (t < 128) {
                    flag_wait(&g_bar[t * 4 + mT], 32);
                    FENCE_ACQ();
                    const char* An = (const char*)&g_hbf[t][mT][0];
#pragma unroll
                    for (int i = 0; i < 3; i++) {
                        int g0 = t * 8 + i;
                        int sg = g0 % 3;
                        mbar_expect(mbS + 16 * sg, 32768);
                        bulk_g2s(sbStage + sg * LCHUNK, An + (size_t)i * 32768, 32768, mbS + 16 * sg);
                    }
                }
            }
            // no trailing __syncthreads: non-tid0 threads block on the phase-tracked mbars
        }
    } else {
        // ================= output worker role: 8 chunks/job =================
        const int wk = bid - 128;   // 0..19
        const u32 mb0 = sb, mb1 = sb + 16;
        const u32 stg = sb + 1024;

        if (tid == 0) {
            mbar_init(mb0, 1);
            mbar_init(mb1, 1);
            asm volatile("fence.proxy.async.shared::cta;" ::: "memory");
        }
        __syncthreads();

        u32 ph0 = 0, ph1 = 0;

        for (int job = wk; job < 1024; job += 20) {
            const int t   = (job >> 3) + 1;       // h step 1..128
            const int mT  = job & 3;
            const int nOT = (job >> 2) & 1;

            if (tid == 0) {
                const u32* bp = &g_bar[t * 4 + mT];
                u32 v;
                asm volatile("ld.relaxed.gpu.global.u32 %0, [%1];" : "=r"(v) : "l"(bp) : "memory");
                while (v < 32) {
                    asm volatile("nanosleep.u32 64;");
                    asm volatile("ld.relaxed.gpu.global.u32 %0, [%1];" : "=r"(v) : "l"(bp) : "memory");
                }
                FENCE_ACQ();
            }
            __syncthreads();

            const char* srcA = (const char*)&g_hbf[t][mT][0];   // 32KB chunks contiguous
            const char* srcB = (const char*)&g_obf[nOT][0][0];  // hi-only, 32KB chunks contiguous

            if (tid == 0) {
#pragma unroll
                for (int pc = 0; pc < 2; pc++) {
                    u32 mbs = pc ? mb1 : mb0;
                    u32 st = stg + pc * OSTG;
                    mbar_expect(mbs, 65536);
                    bulk_g2s(st, srcA + (size_t)pc * 32768, 32768, mbs);
                    bulk_g2s(st + 32768, srcB + (size_t)pc * 32768, 32768, mbs);
                }
            }

            float d[4][4][4];
#pragma unroll
            for (int mi = 0; mi < 4; mi++)
#pragma unroll
                for (int nj = 0; nj < 4; nj++)
#pragma unroll
                    for (int q = 0; q < 4; q++) d[mi][nj][q] = 0.f;

            for (int c = 0; c < 8; c++) {
                int s = c & 1;
                u32 mbs = s ? mb1 : mb0;
                if (s) { mbar_wait(mb1, ph1); ph1 ^= 1; }
                else   { mbar_wait(mb0, ph0); ph0 ^= 1; }
                u32 stA0 = stg + s * OSTG;
                u32 stB0 = stA0 + 32768;
#pragma unroll
                for (int half = 0; half < 2; half++) {
                    u32 stA = stA0 + half * 16384;
                    u32 stB = stB0 + half * 16384;
#pragma unroll
                    for (int k16 = 0; k16 < 4; k16++) {
                        u32 aH[4][4];
#pragma unroll
                        for (int mi = 0; mi < 4; mi++) {
                            u32 off = swz((u32)((wm * 64 + mi * 16 + aRow) * 128 + (k16 * 2 + aKh) * 16));
                            ldsm4(aH[mi], stA + off);
                        }
                        u32 bH[2][4];
#pragma unroll
                        for (int bi = 0; bi < 2; bi++) {
                            u32 off = swz((u32)((wn * 32 + bi * 16 + bRow) * 128 + (k16 * 2 + bKh) * 16));
                            ldsm4(bH[bi], stB + off);
                        }
#pragma unroll
                        for (int mi = 0; mi < 4; mi++)
#pragma unroll
                            for (int nj = 0; nj < 4; nj++)
                                mma_f16(d[mi][nj], aH[mi], &bH[nj >> 1][(nj & 1) * 2]);
                    }
                }
                __syncthreads();
                if (tid == 0 && c + 2 < 8) {
                    int cn = c + 2;
                    mbar_expect(mbs, 65536);
                    bulk_g2s(stA0, srcA + (size_t)cn * 32768, 32768, mbs);
                    bulk_g2s(stB0, srcB + (size_t)cn * 32768, 32768, mbs);
                }
            }

#pragma unroll
            for (int mi = 0; mi < 4; mi++)
#pragma unroll
                for (int nj = 0; nj < 4; nj++)
#pragma unroll
                    for (int rh = 0; rh < 2; rh++) {
                        int bl = wm * 64 + mi * 16 + (lane >> 2) + rh * 8;
                        int b = mT * 128 + bl;
                        int o = nOT * 128 + wn * 32 + nj * 8 + 2 * (lane & 3);
                        float2 v = make_float2(d[mi][nj][rh * 2 + 0] + bout[o],
                                               d[mi][nj][rh * 2 + 1] + bout[o + 1]);
                        *(float2*)&out[(size_t)b * 32768 + (size_t)(t - 1) * 256 + o] = v;
                    }
        }
    }
}

// ---------------- launch ----------------
extern "C" void kernel_launch(void* const* d_in, const int* in_sizes, int n_in,
                              void* d_out, int out_size)
{
    const float *enc = nullptr, *Wih = nullptr, *Whh = nullptr;
    const float *bih = nullptr, *bhh = nullptr, *Wout = nullptr, *bout = nullptr;
    for (int i = 0; i < n_in; i++) {
        int s = in_sizes[i];
        if      (s == 512 * 1024)  enc  = (const float*)d_in[i];
        else if (s == 4096 * 256)  Wih  = (const float*)d_in[i];
        else if (s == 4096 * 1024) Whh  = (const float*)d_in[i];
        else if (s == 4096)        { if (!bih) bih = (const float*)d_in[i]; else bhh = (const float*)d_in[i]; }
        else if (s == 256 * 1024)  Wout = (const float*)d_in[i];
        else if (s == 256)         bout = (const float*)d_in[i];
    }
    if (!enc || !Wih || !Whh || !bih || !bhh || !Wout || !bout) return;

    cudaFuncSetAttribute(persist, cudaFuncAttributeMaxDynamicSharedMemorySize, LSTM_SMEM);

    conv_all<<<1316, 256>>>(Whh, Wih, Wout, enc, bih, bhh, bout);
    persist<<<148, 256, LSTM_SMEM>>>(Whh, bout, (float*)d_out);
    (void)out_size;
}